// round 2
// baseline (speedup 1.0000x reference)
#include <cuda_runtime.h>
#include <math.h>
#include <stdint.h>

#define BB 2
#define NN 8192
#define KK 16

// ---------------- scratch (static device globals; no allocation) ----------------
__device__ float4 g_cpack[BB*NN];
__device__ int    g_idx [BB*NN*KK];
__device__ float  g_dist[BB*NN*KK];
__device__ float  g_y1   [BB*64 *NN];   // mlp1 out -> normalized x1 (in place)
__device__ float  g_pool1[BB*64 *NN];   // attentive pool1, sf half
__device__ float  g_y2   [BB*32 *NN];   // mlpp1 out -> normalized x2
__device__ float  g_pool2[BB*32 *NN];   // attentive pool2, sf half
__device__ float  g_ymain[BB*128*NN];   // mlp2 raw
__device__ float  g_yres [BB*128*NN];   // res raw
__device__ double g_mpart[256*65];      // spatial moment partials
__device__ float  g_sc1[64],  g_sh1[64];
__device__ float  g_sc2[32],  g_sh2[32];
__device__ float  g_scm[128], g_shm[128];
__device__ float  g_scrs[128],g_shrs[128];
__device__ float  g_l1sc[64], g_l1sh[64];
__device__ float  g_l2sc[32], g_l2sh[32];

// ---------------- pack coords + squared norm ----------------
__global__ void __launch_bounds__(256) pack_kernel(const float* __restrict__ coords) {
    int p = (blockIdx.x << 8) + threadIdx.x;          // < BB*NN
    float x = coords[p*3+0], y = coords[p*3+1], z = coords[p*3+2];
    g_cpack[p] = make_float4(x, y, z, fmaf(x, x, fmaf(y, y, z*z)));
}

// ---------------- KNN: warp per query, thresholded buffer select ----------------
__device__ __forceinline__ void warp_merge(float* md, int* mi,
                                           float* topd, int* topi,
                                           int lane, int& cnt, float& tau) {
    const float INF = __int_as_float(0x7f800000);
    for (int s = cnt; s < 6; s++) md[lane*6 + s] = INF;
    if (lane < 16) { md[192 + lane] = topd[lane]; mi[192 + lane] = topi[lane]; }
    __syncwarp();
    #pragma unroll 1
    for (int r = 0; r < 16; r++) {
        float v = md[lane]; int p = lane;
        #pragma unroll
        for (int e = 1; e < 7; e++) {
            int q = lane + e*32;
            float x = md[q];
            if (x < v) { v = x; p = q; }
        }
        #pragma unroll
        for (int off = 16; off; off >>= 1) {
            float v2 = __shfl_xor_sync(0xffffffffu, v, off);
            int   p2 = __shfl_xor_sync(0xffffffffu, p, off);
            if (v2 < v || (v2 == v && p2 < p)) { v = v2; p = p2; }
        }
        if (lane == 0) { topd[r] = v; topi[r] = mi[p]; md[p] = INF; }
        __syncwarp();
    }
    cnt = 0;
    tau = topd[15];
    __syncwarp();
}

__global__ void __launch_bounds__(256) knn_kernel() {
    __shared__ __align__(16) float4 tile[2048];      // 32 KB
    __shared__ float smd[8][224];                    // 192 buf + 16 top + 16 pad
    __shared__ int   smi[8][224];
    __shared__ float stopd[8][16];
    __shared__ int   stopi[8][16];

    const float INF = __int_as_float(0x7f800000);
    const int tid = threadIdx.x, w = tid >> 5, lane = tid & 31;
    const int blk = blockIdx.x;                      // 0..2047
    const int b   = blk >> 10;
    const int n   = ((blk & 1023) << 3) | w;

    float* md   = smd[w];   int* mi   = smi[w];
    float* topd = stopd[w]; int* topi = stopi[w];

    if (lane < 16) { topd[lane] = INF; topi[lane] = 0; md[208 + lane] = INF; }
    const float4 ci = g_cpack[(b << 13) + n];
    float tau = INF;
    int cnt = 0;
    __syncwarp();

    for (int t = 0; t < 4; t++) {
        __syncthreads();
        for (int q = tid; q < 2048; q += 256)
            tile[q] = g_cpack[(b << 13) + (t << 11) + q];
        __syncthreads();
        #pragma unroll 1
        for (int q = lane; q < 2048; q += 32) {
            float4 cj = tile[q];
            float dot = fmaf(ci.x, cj.x, fmaf(ci.y, cj.y, ci.z * cj.z));
            float d2  = fmaf(-2.f, dot, ci.w + cj.w);
            int j = (t << 11) + q;
            if ((j != n) && (d2 < tau)) {
                md[lane*6 + cnt] = d2;
                mi[lane*6 + cnt] = j;
                cnt++;
            }
            if (__ballot_sync(0xffffffffu, cnt == 6))
                warp_merge(md, mi, topd, topi, lane, cnt, tau);
        }
    }
    warp_merge(md, mi, topd, topi, lane, cnt, tau);
    if (lane < 16) {
        int gofs = ((((b << 13) | n)) << 4) | lane;
        g_idx [gofs] = topi[lane];
        g_dist[gofs] = fmaxf(topd[lane], 0.0f);
    }
}

// ---------------- generic 1x1 conv (channel GEMM), 32 outputs / thread ----------------
template<int CI, int CI0>
__global__ void __launch_bounds__(256) conv1x1_kernel(
    const float* __restrict__ in0, const float* __restrict__ in1,
    const float* __restrict__ W,   const float* __restrict__ bias,
    float* __restrict__ y, int CO) {
    __shared__ float Wsh[CI*32];
    __shared__ float bsh[32];
    const int oc0 = blockIdx.y << 5;
    for (int t = threadIdx.x; t < CI*32; t += 256) {
        int i = t >> 5, ol = t & 31;
        Wsh[t] = W[(oc0 + ol)*CI + i];
    }
    if (threadIdx.x < 32) bsh[threadIdx.x] = bias[oc0 + threadIdx.x];
    __syncthreads();
    const int p = (blockIdx.x << 8) + threadIdx.x;   // < BB*NN
    const int b = p >> 13, n = p & (NN-1);
    float acc[32];
    #pragma unroll
    for (int o = 0; o < 32; o++) acc[o] = bsh[o];
    #pragma unroll 4
    for (int i = 0; i < CI0; i++) {
        float x = in0[((b*CI0 + i) << 13) + n];
        #pragma unroll
        for (int o = 0; o < 32; o++) acc[o] = fmaf(Wsh[(i << 5) + o], x, acc[o]);
    }
    if (CI > CI0) {
        #pragma unroll 4
        for (int i = 0; i < CI - CI0; i++) {
            float x = in1[((b*(CI-CI0) + i) << 13) + n];
            #pragma unroll
            for (int o = 0; o < 32; o++) acc[o] = fmaf(Wsh[((CI0 + i) << 5) + o], x, acc[o]);
        }
    }
    #pragma unroll
    for (int o = 0; o < 32; o++)
        y[((b*CO + oc0 + o) << 13) + n] = acc[o];
}

// ---------------- BN stats per channel (training mode, exact two-pass) ----------------
__global__ void __launch_bounds__(256) bn_stats_kernel(
    const float* __restrict__ y, int CO,
    const float* __restrict__ g, const float* __restrict__ bt,
    float* __restrict__ scale, float* __restrict__ shift) {
    const int o = blockIdx.x;
    double s = 0.0, s2 = 0.0;
    for (int p = threadIdx.x; p < BB*NN; p += 256) {
        int b = p >> 13, n = p & (NN-1);
        float v = y[((b*CO + o) << 13) + n];
        s += (double)v; s2 += (double)v * (double)v;
    }
    __shared__ double sh[512];
    sh[threadIdx.x] = s; sh[256 + threadIdx.x] = s2;
    __syncthreads();
    for (int st = 128; st > 0; st >>= 1) {
        if (threadIdx.x < st) {
            sh[threadIdx.x]     += sh[threadIdx.x + st];
            sh[256+threadIdx.x] += sh[256 + threadIdx.x + st];
        }
        __syncthreads();
    }
    if (threadIdx.x == 0) {
        const double P = (double)(BB*NN);
        double mean = sh[0]/P;
        double var  = sh[256]/P - mean*mean;
        double rs   = 1.0 / sqrt(var + 1e-5);
        double scl  = (double)g[o] * rs;
        scale[o] = (float)scl;
        shift[o] = (float)((double)bt[o] - mean*scl);
    }
}

// ---------------- normalize + activation ----------------
__global__ void __launch_bounds__(256) bn_act_kernel(
    float* __restrict__ y, const float* __restrict__ scale,
    const float* __restrict__ shift, int CO, float slope) {
    int t = (blockIdx.x << 8) + threadIdx.x;   // < BB*CO*NN
    int o = (t >> 13) % CO;
    float v = fmaf(y[t], scale[o], shift[o]);
    y[t] = v > 0.f ? v : slope*v;
}

// ---------------- spatial moments (shared by lse1 & lse2 BN) ----------------
__global__ void __launch_bounds__(256) moments_kernel() {
    const int tid = threadIdx.x;
    float a[65];
    #pragma unroll
    for (int v = 0; v < 65; v++) a[v] = 0.f;
    const int p0 = (((blockIdx.x << 8) + tid) << 2);
    for (int q = 0; q < 4; q++) {
        int p  = p0 + q;
        int bn = p >> 4;
        int b  = bn >> 13;
        int j  = g_idx[p];
        float d = g_dist[p];
        float4 ct = g_cpack[bn];
        float4 nb = g_cpack[(b << 13) + j];
        float s[10] = { ct.x, ct.y, ct.z, nb.x, nb.y, nb.z,
                        ct.x-nb.x, ct.y-nb.y, ct.z-nb.z, d };
        int c2 = 10;
        #pragma unroll
        for (int i = 0; i < 10; i++) {
            a[i] += s[i];
            #pragma unroll
            for (int j2 = i; j2 < 10; j2++) { a[c2] = fmaf(s[i], s[j2], a[c2]); c2++; }
        }
    }
    __shared__ double sacc[65];
    if (tid < 65) sacc[tid] = 0.0;
    __syncthreads();
    #pragma unroll
    for (int v = 0; v < 65; v++) {
        float x = a[v];
        #pragma unroll
        for (int off = 16; off; off >>= 1) x += __shfl_down_sync(0xffffffffu, x, off);
        if ((tid & 31) == 0) atomicAdd(&sacc[v], (double)x);
    }
    __syncthreads();
    if (tid < 65) g_mpart[blockIdx.x*65 + tid] = sacc[tid];
}

// ---------------- finalize lse BN params: mean = w·m + b, var = w^T C w ----------------
__global__ void finalize_lse_kernel(
    const float* __restrict__ w1, const float* __restrict__ b1,
    const float* __restrict__ g1, const float* __restrict__ bt1,
    const float* __restrict__ w2, const float* __restrict__ b2,
    const float* __restrict__ g2, const float* __restrict__ bt2) {
    __shared__ double M[65];
    __shared__ double mm[10];
    __shared__ double Cv[10][10];
    const int tid = threadIdx.x;
    if (tid < 65) {
        double s = 0.0;
        for (int q = 0; q < 256; q++) s += g_mpart[q*65 + tid];
        M[tid] = s;
    }
    __syncthreads();
    const double P = (double)BB * NN * KK;
    if (tid < 10) mm[tid] = M[tid] / P;
    __syncthreads();
    if (tid < 100) {
        int i = tid/10, j = tid%10;
        if (j >= i) {
            int off = 10 + i*10 - (i*(i-1))/2 + (j - i);
            double c = M[off]/P - mm[i]*mm[j];
            Cv[i][j] = c; Cv[j][i] = c;
        }
    }
    __syncthreads();
    if (tid < 64) {
        int o = tid;
        double wv[10];
        for (int i = 0; i < 10; i++) wv[i] = (double)w1[o*10 + i];
        double mean = (double)b1[o];
        for (int i = 0; i < 10; i++) mean += wv[i]*mm[i];
        double var = 0.0;
        for (int i = 0; i < 10; i++) {
            double t = 0.0;
            for (int j = 0; j < 10; j++) t += wv[j]*Cv[i][j];
            var += wv[i]*t;
        }
        double scl = (double)g1[o] / sqrt(var + 1e-5);
        g_l1sc[o] = (float)scl;
        g_l1sh[o] = (float)((double)bt1[o] - mean*scl);
    } else if (tid < 96) {
        int o = tid - 64;
        double wv[10];
        for (int i = 0; i < 10; i++) wv[i] = (double)w2[o*10 + i];
        double mean = (double)b2[o];
        for (int i = 0; i < 10; i++) mean += wv[i]*mm[i];
        double var = 0.0;
        for (int i = 0; i < 10; i++) {
            double t = 0.0;
            for (int j = 0; j < 10; j++) t += wv[j]*Cv[i][j];
            var += wv[i]*t;
        }
        double scl = (double)g2[o] / sqrt(var + 1e-5);
        g_l2sc[o] = (float)scl;
        g_l2sh[o] = (float)((double)bt2[o] - mean*scl);
    }
}

// ---------------- fused LSE (gather + 10->C MLP + BN + ReLU) + attentive pool ----------------
// feat half is constant over K: its score term cancels in softmax, and pooled
// feat channels == feat (handled downstream). Only sf channels computed here.
template<int C>
__global__ void __launch_bounds__(C == 64 ? 128 : 256) lse_pool_kernel(
    const float* __restrict__ Wl,  const float* __restrict__ bl,
    const float* __restrict__ lsc, const float* __restrict__ lsh,
    const float* __restrict__ Wp,  float* __restrict__ pooled) {
    constexpr int WARPS = (C == 64) ? 4 : 8;
    constexpr int CPT   = C / 32;
    constexpr int NT    = WARPS * 32;
    __shared__ float wl_sh[10 * C];
    __shared__ float wp_sh[C * C];        // transposed: [c][o]
    __shared__ float prm_sh[3 * C];
    __shared__ __align__(16) float s_sh[WARPS][16][12];
    __shared__ __align__(16) float h_sh[WARPS][C * 16];   // [c][k]

    const int tid = threadIdx.x;
    for (int t = tid; t < 10*C; t += NT) { int i = t / C, c = t % C; wl_sh[t] = Wl[c*10 + i]; }
    for (int t = tid; t < C*C;  t += NT) { int c = t / C, o = t % C; wp_sh[t] = Wp[o*(2*C) + c]; }
    for (int t = tid; t < C;    t += NT) { prm_sh[t] = bl[t]; prm_sh[C+t] = lsc[t]; prm_sh[2*C+t] = lsh[t]; }
    __syncthreads();

    const int w = tid >> 5, lane = tid & 31;
    const int pt = blockIdx.x * WARPS + w;   // b*NN + n
    const int b  = pt >> 13;
    const int n  = pt & (NN-1);

    // phase 1: gather spatial features (k = lane for lane<16)
    if (lane < 16) {
        int gofs = (pt << 4) | lane;
        int j    = g_idx[gofs];
        float d  = g_dist[gofs];
        float4 ct = g_cpack[pt];
        float4 nb = g_cpack[(b << 13) + j];
        float* sr = s_sh[w][lane];
        sr[0]=ct.x; sr[1]=ct.y; sr[2]=ct.z;
        sr[3]=nb.x; sr[4]=nb.y; sr[5]=nb.z;
        sr[6]=ct.x-nb.x; sr[7]=ct.y-nb.y; sr[8]=ct.z-nb.z;
        sr[9]=d; sr[10]=0.f; sr[11]=0.f;
    }
    __syncwarp();

    // phase 2: 10->C MLP + BN + ReLU -> h_sh[c][k]
    {
        float wlr[CPT][10], br[CPT], scr[CPT], shr[CPT];
        #pragma unroll
        for (int cc = 0; cc < CPT; cc++) {
            int c = lane + 32*cc;
            #pragma unroll
            for (int i = 0; i < 10; i++) wlr[cc][i] = wl_sh[i*C + c];
            br[cc] = prm_sh[c]; scr[cc] = prm_sh[C + c]; shr[cc] = prm_sh[2*C + c];
        }
        #pragma unroll
        for (int k = 0; k < 16; k++) {
            const float4* sp = (const float4*)s_sh[w][k];
            float4 a0 = sp[0], a1 = sp[1], a2 = sp[2];
            float sv[10] = { a0.x,a0.y,a0.z,a0.w, a1.x,a1.y,a1.z,a1.w, a2.x,a2.y };
            #pragma unroll
            for (int cc = 0; cc < CPT; cc++) {
                float yv = br[cc];
                #pragma unroll
                for (int i = 0; i < 10; i++) yv = fmaf(wlr[cc][i], sv[i], yv);
                float v = fmaf(yv, scr[cc], shr[cc]);
                h_sh[w][(lane + 32*cc)*16 + k] = fmaxf(v, 0.f);
            }
        }
    }
    __syncwarp();

    // phase 3: score GEMM  scores[o][k] = sum_c Wp[o,c] h[c][k]  (bias/feat cancel)
    float acc[CPT][16];
    #pragma unroll
    for (int cc = 0; cc < CPT; cc++)
        #pragma unroll
        for (int k = 0; k < 16; k++) acc[cc][k] = 0.f;

    #pragma unroll 4
    for (int c = 0; c < C; c++) {
        const float4* hp = (const float4*)&h_sh[w][c*16];
        float hv[16];
        *(float4*)&hv[0]  = hp[0]; *(float4*)&hv[4]  = hp[1];
        *(float4*)&hv[8]  = hp[2]; *(float4*)&hv[12] = hp[3];
        #pragma unroll
        for (int cc = 0; cc < CPT; cc++) {
            float wv = wp_sh[c*C + lane + 32*cc];
            #pragma unroll
            for (int k = 0; k < 16; k++) acc[cc][k] = fmaf(wv, hv[k], acc[cc][k]);
        }
    }

    // phase 4: softmax over K + weighted sum
    #pragma unroll
    for (int cc = 0; cc < CPT; cc++) {
        int o = lane + 32*cc;
        float m = acc[cc][0];
        #pragma unroll
        for (int k = 1; k < 16; k++) m = fmaxf(m, acc[cc][k]);
        float se = 0.f;
        #pragma unroll
        for (int k = 0; k < 16; k++) { acc[cc][k] = __expf(acc[cc][k] - m); se += acc[cc][k]; }
        const float4* hp = (const float4*)&h_sh[w][o*16];
        float hv[16];
        *(float4*)&hv[0]  = hp[0]; *(float4*)&hv[4]  = hp[1];
        *(float4*)&hv[8]  = hp[2]; *(float4*)&hv[12] = hp[3];
        float sum = 0.f;
        #pragma unroll
        for (int k = 0; k < 16; k++) sum = fmaf(acc[cc][k], hv[k], sum);
        pooled[((b*C + o) << 13) + n] = sum / se;
    }
}

// ---------------- final: BN + ReLU on mlp2 & res, concat write (leaky0.01 ∘ relu = relu) ----
__global__ void __launch_bounds__(256) final_kernel(float* __restrict__ out) {
    int t = (blockIdx.x << 8) + threadIdx.x;   // < BB*256*NN
    int b  = t >> 21;
    int r  = t & ((1 << 21) - 1);
    int ch = r >> 13;
    int n  = r & (NN-1);
    float v;
    if (ch < 128) v = fmaf(g_ymain[((b*128 + ch) << 13) + n], g_scm[ch], g_shm[ch]);
    else { int c = ch - 128; v = fmaf(g_yres[((b*128 + c) << 13) + n], g_scrs[c], g_shrs[c]); }
    out[t] = fmaxf(v, 0.f);
}

// ---------------- launch ----------------
extern "C" void kernel_launch(void* const* d_in, const int* in_sizes, int n_in,
                              void* d_out, int out_size) {
    const float* coords   = (const float*)d_in[0];
    const float* features = (const float*)d_in[1];
    const float* mlp1_w  = (const float*)d_in[2];
    const float* mlp1_b  = (const float*)d_in[3];
    const float* mlp1_g  = (const float*)d_in[4];
    const float* mlp1_bt = (const float*)d_in[5];
    const float* lse1_w  = (const float*)d_in[6];
    const float* lse1_b  = (const float*)d_in[7];
    const float* lse1_g  = (const float*)d_in[8];
    const float* lse1_bt = (const float*)d_in[9];
    const float* mlpp1_w  = (const float*)d_in[10];
    const float* mlpp1_b  = (const float*)d_in[11];
    const float* mlpp1_g  = (const float*)d_in[12];
    const float* mlpp1_bt = (const float*)d_in[13];
    const float* lse2_w  = (const float*)d_in[14];
    const float* lse2_b  = (const float*)d_in[15];
    const float* lse2_g  = (const float*)d_in[16];
    const float* lse2_bt = (const float*)d_in[17];
    const float* mlp2_w  = (const float*)d_in[18];
    const float* mlp2_b  = (const float*)d_in[19];
    const float* mlp2_g  = (const float*)d_in[20];
    const float* mlp2_bt = (const float*)d_in[21];
    const float* res_w  = (const float*)d_in[22];
    const float* res_b  = (const float*)d_in[23];
    const float* res_g  = (const float*)d_in[24];
    const float* res_bt = (const float*)d_in[25];
    const float* pool1_w = (const float*)d_in[26];
    // d_in[27] = pool1_b (cancels in softmax; pooled feat half is identity)
    const float* pool2_w = (const float*)d_in[28];
    // d_in[29] = pool2_b
    float* out = (float*)d_out;

    void *p_y1, *p_pool1, *p_y2, *p_pool2, *p_ymain, *p_yres;
    void *p_sc1, *p_sh1, *p_sc2, *p_sh2, *p_scm, *p_shm, *p_scrs, *p_shrs;
    void *p_l1sc, *p_l1sh, *p_l2sc, *p_l2sh;
    cudaGetSymbolAddress(&p_y1, g_y1);       cudaGetSymbolAddress(&p_pool1, g_pool1);
    cudaGetSymbolAddress(&p_y2, g_y2);       cudaGetSymbolAddress(&p_pool2, g_pool2);
    cudaGetSymbolAddress(&p_ymain, g_ymain); cudaGetSymbolAddress(&p_yres, g_yres);
    cudaGetSymbolAddress(&p_sc1, g_sc1);     cudaGetSymbolAddress(&p_sh1, g_sh1);
    cudaGetSymbolAddress(&p_sc2, g_sc2);     cudaGetSymbolAddress(&p_sh2, g_sh2);
    cudaGetSymbolAddress(&p_scm, g_scm);     cudaGetSymbolAddress(&p_shm, g_shm);
    cudaGetSymbolAddress(&p_scrs, g_scrs);   cudaGetSymbolAddress(&p_shrs, g_shrs);
    cudaGetSymbolAddress(&p_l1sc, g_l1sc);   cudaGetSymbolAddress(&p_l1sh, g_l1sh);
    cudaGetSymbolAddress(&p_l2sc, g_l2sc);   cudaGetSymbolAddress(&p_l2sh, g_l2sh);

    // geometry
    pack_kernel<<<64, 256>>>(coords);
    knn_kernel<<<2048, 256>>>();
    moments_kernel<<<256, 256>>>();
    finalize_lse_kernel<<<1, 128>>>(lse1_w, lse1_b, lse1_g, lse1_bt,
                                    lse2_w, lse2_b, lse2_g, lse2_bt);

    // mlp1: features(32) -> 64, BN + leaky(0.2)
    conv1x1_kernel<32,32><<<dim3(64,2), 256>>>(features, nullptr, mlp1_w, mlp1_b, (float*)p_y1, 64);
    bn_stats_kernel<<<64, 256>>>((float*)p_y1, 64, mlp1_g, mlp1_bt, (float*)p_sc1, (float*)p_sh1);
    bn_act_kernel<<<4096, 256>>>((float*)p_y1, (float*)p_sc1, (float*)p_sh1, 64, 0.2f);

    // lse1 + pool1 (sf half only)
    lse_pool_kernel<64><<<4096, 128>>>(lse1_w, lse1_b, (float*)p_l1sc, (float*)p_l1sh,
                                       pool1_w, (float*)p_pool1);

    // mlpp1: [pool1_sf(64); x1(64)] -> 32, BN + relu
    conv1x1_kernel<128,64><<<dim3(64,1), 256>>>((float*)p_pool1, (float*)p_y1, mlpp1_w, mlpp1_b, (float*)p_y2, 32);
    bn_stats_kernel<<<32, 256>>>((float*)p_y2, 32, mlpp1_g, mlpp1_bt, (float*)p_sc2, (float*)p_sh2);
    bn_act_kernel<<<2048, 256>>>((float*)p_y2, (float*)p_sc2, (float*)p_sh2, 32, 0.0f);

    // lse2 + pool2
    lse_pool_kernel<32><<<2048, 256>>>(lse2_w, lse2_b, (float*)p_l2sc, (float*)p_l2sh,
                                       pool2_w, (float*)p_pool2);

    // mlp2: [pool2_sf(32); x2(32)] -> 128
    conv1x1_kernel<64,32><<<dim3(64,4), 256>>>((float*)p_pool2, (float*)p_y2, mlp2_w, mlp2_b, (float*)p_ymain, 128);
    bn_stats_kernel<<<128, 256>>>((float*)p_ymain, 128, mlp2_g, mlp2_bt, (float*)p_scm, (float*)p_shm);

    // residual: features(32) -> 128
    conv1x1_kernel<32,32><<<dim3(64,4), 256>>>(features, nullptr, res_w, res_b, (float*)p_yres, 128);
    bn_stats_kernel<<<128, 256>>>((float*)p_yres, 128, res_g, res_bt, (float*)p_scrs, (float*)p_shrs);

    // fused BN + ReLU + concat (+ identity leaky 0.01)
    final_kernel<<<16384, 256>>>(out);
}

// round 3
// speedup vs baseline: 1.1282x; 1.1282x over previous
#include <cuda_runtime.h>
#include <math.h>
#include <stdint.h>

#define BB 2
#define NN 8192
#define KK 16

// ---------------- scratch (static device globals; no allocation) ----------------
__device__ float4 g_cpack[BB*NN];
__device__ int    g_idx [BB*NN*KK];
__device__ float  g_dist[BB*NN*KK];
__device__ float  g_y1   [BB*64 *NN];   // mlp1 raw conv out
__device__ float  g_pool1[BB*64 *NN];   // attentive pool1, sf half
__device__ float  g_y2   [BB*32 *NN];   // mlpp1 raw conv out
__device__ float  g_pool2[BB*32 *NN];   // attentive pool2, sf half
__device__ float  g_ymain[BB*128*NN];   // mlp2 raw
__device__ float  g_yres [BB*128*NN];   // res raw
__device__ double g_mpart[256*65];      // spatial moment partials
__device__ double g_csum [352];         // fused BN sums:  [0,64)=mlp1 [64,96)=mlpp1 [96,224)=mlp2 [224,352)=res
__device__ double g_csum2[352];
__device__ float  g_sc1[64],  g_sh1[64];
__device__ float  g_sc2[32],  g_sh2[32];
__device__ float  g_scm[128], g_shm[128];
__device__ float  g_scrs[128],g_shrs[128];
__device__ float  g_l1sc[64], g_l1sh[64];
__device__ float  g_l2sc[32], g_l2sh[32];

// ---------------- pack coords + squared norm; zero BN accumulators ----------------
__global__ void __launch_bounds__(256) pack_kernel(const float* __restrict__ coords) {
    int p = (blockIdx.x << 8) + threadIdx.x;          // < BB*NN
    float x = coords[p*3+0], y = coords[p*3+1], z = coords[p*3+2];
    g_cpack[p] = make_float4(x, y, z, fmaf(x, x, fmaf(y, y, z*z)));
    if (p < 352) { g_csum[p] = 0.0; g_csum2[p] = 0.0; }
}

// ---------------- KNN: warp per query, thresholded buffer select ----------------
__device__ __forceinline__ void warp_merge(float* md, int* mi,
                                           float* topd, int* topi,
                                           int lane, int& cnt, float& tau) {
    const float INF = __int_as_float(0x7f800000);
    for (int s = cnt; s < 6; s++) md[lane*6 + s] = INF;
    if (lane < 16) { md[192 + lane] = topd[lane]; mi[192 + lane] = topi[lane]; }
    __syncwarp();
    #pragma unroll 1
    for (int r = 0; r < 16; r++) {
        float v = md[lane]; int p = lane;
        #pragma unroll
        for (int e = 1; e < 7; e++) {
            int q = lane + e*32;
            float x = md[q];
            if (x < v) { v = x; p = q; }
        }
        #pragma unroll
        for (int off = 16; off; off >>= 1) {
            float v2 = __shfl_xor_sync(0xffffffffu, v, off);
            int   p2 = __shfl_xor_sync(0xffffffffu, p, off);
            if (v2 < v || (v2 == v && p2 < p)) { v = v2; p = p2; }
        }
        if (lane == 0) { topd[r] = v; topi[r] = mi[p]; md[p] = INF; }
        __syncwarp();
    }
    cnt = 0;
    tau = topd[15];
    __syncwarp();
}

__global__ void __launch_bounds__(256) knn_kernel() {
    __shared__ __align__(16) float4 tile[2048];      // 32 KB
    __shared__ float smd[8][224];
    __shared__ int   smi[8][224];
    __shared__ float stopd[8][16];
    __shared__ int   stopi[8][16];

    const float INF = __int_as_float(0x7f800000);
    const int tid = threadIdx.x, w = tid >> 5, lane = tid & 31;
    const int blk = blockIdx.x;                      // 0..2047
    const int b   = blk >> 10;
    const int n   = ((blk & 1023) << 3) | w;

    float* md   = smd[w];   int* mi   = smi[w];
    float* topd = stopd[w]; int* topi = stopi[w];

    if (lane < 16) { topd[lane] = INF; topi[lane] = 0; md[208 + lane] = INF; }
    const float4 ci = g_cpack[(b << 13) + n];
    float tau = INF;
    int cnt = 0;
    __syncwarp();

    for (int t = 0; t < 4; t++) {
        __syncthreads();
        for (int q = tid; q < 2048; q += 256)
            tile[q] = g_cpack[(b << 13) + (t << 11) + q];
        __syncthreads();
        #pragma unroll 1
        for (int q = lane; q < 2048; q += 32) {
            float4 cj = tile[q];
            float dot = fmaf(ci.x, cj.x, fmaf(ci.y, cj.y, ci.z * cj.z));
            float d2  = fmaf(-2.f, dot, ci.w + cj.w);
            int j = (t << 11) + q;
            if ((j != n) && (d2 < tau)) {
                md[lane*6 + cnt] = d2;
                mi[lane*6 + cnt] = j;
                cnt++;
            }
            if (__ballot_sync(0xffffffffu, cnt == 6))
                warp_merge(md, mi, topd, topi, lane, cnt, tau);
        }
    }
    warp_merge(md, mi, topd, topi, lane, cnt, tau);
    if (lane < 16) {
        int gofs = ((((b << 13) | n)) << 4) | lane;
        g_idx [gofs] = topi[lane];
        g_dist[gofs] = fmaxf(topd[lane], 0.0f);
    }
}

// ---------------- 1x1 conv (channel GEMM), 32 outputs/thread, fused BN-stat reduce ----------
// ACT1: apply scale/shift + leaky(slope) to in1 channels at read time.
template<int CI, int CI0, bool ACT1>
__global__ void __launch_bounds__(256) conv1x1_kernel(
    const float* __restrict__ in0, const float* __restrict__ in1,
    const float* __restrict__ W,   const float* __restrict__ bias,
    const float* __restrict__ sc1, const float* __restrict__ sh1, float slope,
    float* __restrict__ y, int CO, int acc_off) {
    __shared__ float Wsh[CI*32];
    __shared__ float bsh[32];
    __shared__ float scsh[ACT1 ? (CI-CI0) : 1], shsh[ACT1 ? (CI-CI0) : 1];
    __shared__ float red_s[8][32], red_q[8][32];
    const int oc0 = blockIdx.y << 5;
    for (int t = threadIdx.x; t < CI*32; t += 256) {
        int i = t >> 5, ol = t & 31;
        Wsh[t] = W[(oc0 + ol)*CI + i];
    }
    if (threadIdx.x < 32) bsh[threadIdx.x] = bias[oc0 + threadIdx.x];
    if (ACT1 && threadIdx.x < (CI-CI0)) {
        scsh[threadIdx.x] = sc1[threadIdx.x];
        shsh[threadIdx.x] = sh1[threadIdx.x];
    }
    __syncthreads();
    const int p = (blockIdx.x << 8) + threadIdx.x;   // < BB*NN
    const int b = p >> 13, n = p & (NN-1);
    const int w = threadIdx.x >> 5, lane = threadIdx.x & 31;
    float acc[32];
    #pragma unroll
    for (int o = 0; o < 32; o++) acc[o] = bsh[o];
    #pragma unroll 4
    for (int i = 0; i < CI0; i++) {
        float x = in0[((b*CI0 + i) << 13) + n];
        #pragma unroll
        for (int o = 0; o < 32; o++) acc[o] = fmaf(Wsh[(i << 5) + o], x, acc[o]);
    }
    if (CI > CI0) {
        #pragma unroll 4
        for (int i = 0; i < CI - CI0; i++) {
            float x = in1[((b*(CI-CI0) + i) << 13) + n];
            if (ACT1) {
                x = fmaf(x, scsh[i], shsh[i]);
                x = x > 0.f ? x : slope * x;
            }
            #pragma unroll
            for (int o = 0; o < 32; o++) acc[o] = fmaf(Wsh[((CI0 + i) << 5) + o], x, acc[o]);
        }
    }
    #pragma unroll
    for (int o = 0; o < 32; o++)
        y[((b*CO + oc0 + o) << 13) + n] = acc[o];

    // fused per-channel sum / sumsq reduction
    #pragma unroll
    for (int o = 0; o < 32; o++) {
        float v = acc[o];
        float q = v * v;
        #pragma unroll
        for (int off = 16; off; off >>= 1) {
            v += __shfl_xor_sync(0xffffffffu, v, off);
            q += __shfl_xor_sync(0xffffffffu, q, off);
        }
        if (lane == 0) { red_s[w][o] = v; red_q[w][o] = q; }
    }
    __syncthreads();
    if (threadIdx.x < 64) {
        int o = threadIdx.x & 31, which = threadIdx.x >> 5;
        float s = 0.f;
        #pragma unroll
        for (int ww = 0; ww < 8; ww++) s += which ? red_q[ww][o] : red_s[ww][o];
        atomicAdd(which ? &g_csum2[acc_off + oc0 + o] : &g_csum[acc_off + oc0 + o], (double)s);
    }
}

// ---------------- finalize BN params from fused sums ----------------
__global__ void bnfin_kernel(int off, int CO,
                             const float* __restrict__ g, const float* __restrict__ bt,
                             float* __restrict__ scale, float* __restrict__ shift) {
    int o = threadIdx.x;
    if (o >= CO) return;
    const double P = (double)(BB*NN);
    double mean = g_csum[off + o] / P;
    double var  = g_csum2[off + o] / P - mean*mean;
    double scl  = (double)g[o] / sqrt(var + 1e-5);
    scale[o] = (float)scl;
    shift[o] = (float)((double)bt[o] - mean*scl);
}

// ---------------- spatial moments (shared by lse1 & lse2 BN) ----------------
__global__ void __launch_bounds__(256) moments_kernel() {
    const int tid = threadIdx.x;
    float a[65];
    #pragma unroll
    for (int v = 0; v < 65; v++) a[v] = 0.f;
    const int p0 = (((blockIdx.x << 8) + tid) << 2);
    for (int q = 0; q < 4; q++) {
        int p  = p0 + q;
        int bn = p >> 4;
        int b  = bn >> 13;
        int j  = g_idx[p];
        float d = g_dist[p];
        float4 ct = g_cpack[bn];
        float4 nb = g_cpack[(b << 13) + j];
        float s[10] = { ct.x, ct.y, ct.z, nb.x, nb.y, nb.z,
                        ct.x-nb.x, ct.y-nb.y, ct.z-nb.z, d };
        int c2 = 10;
        #pragma unroll
        for (int i = 0; i < 10; i++) {
            a[i] += s[i];
            #pragma unroll
            for (int j2 = i; j2 < 10; j2++) { a[c2] = fmaf(s[i], s[j2], a[c2]); c2++; }
        }
    }
    __shared__ double sacc[65];
    if (tid < 65) sacc[tid] = 0.0;
    __syncthreads();
    #pragma unroll
    for (int v = 0; v < 65; v++) {
        float x = a[v];
        #pragma unroll
        for (int off = 16; off; off >>= 1) x += __shfl_down_sync(0xffffffffu, x, off);
        if ((tid & 31) == 0) atomicAdd(&sacc[v], (double)x);
    }
    __syncthreads();
    if (tid < 65) g_mpart[blockIdx.x*65 + tid] = sacc[tid];
}

// ---------------- finalize lse BN params: mean = w·m + b, var = w^T C w (parallel) -------
__global__ void __launch_bounds__(1024) finalize_lse_kernel(
    const float* __restrict__ w1, const float* __restrict__ b1,
    const float* __restrict__ g1, const float* __restrict__ bt1,
    const float* __restrict__ w2, const float* __restrict__ b2,
    const float* __restrict__ g2, const float* __restrict__ bt2) {
    __shared__ double M[65];
    __shared__ double mm[10];
    __shared__ double Cv[10][10];
    const int tid = threadIdx.x;
    const int w = tid >> 5, lane = tid & 31;
    // warp-parallel reduction over 256 partials per moment
    for (int v = w; v < 65; v += 32) {
        double s = 0.0;
        for (int q = lane; q < 256; q += 32) s += g_mpart[q*65 + v];
        #pragma unroll
        for (int off = 16; off; off >>= 1) s += __shfl_xor_sync(0xffffffffu, s, off);
        if (lane == 0) M[v] = s;
    }
    __syncthreads();
    const double P = (double)BB * NN * KK;
    if (tid < 10) mm[tid] = M[tid] / P;
    __syncthreads();
    if (tid < 100) {
        int i = tid/10, j = tid%10;
        if (j >= i) {
            int off = 10 + i*10 - (i*(i-1))/2 + (j - i);
            double c = M[off]/P - mm[i]*mm[j];
            Cv[i][j] = c; Cv[j][i] = c;
        }
    }
    __syncthreads();
    if (tid < 64) {
        int o = tid;
        double wv[10];
        for (int i = 0; i < 10; i++) wv[i] = (double)w1[o*10 + i];
        double mean = (double)b1[o];
        for (int i = 0; i < 10; i++) mean += wv[i]*mm[i];
        double var = 0.0;
        for (int i = 0; i < 10; i++) {
            double t = 0.0;
            for (int j = 0; j < 10; j++) t += wv[j]*Cv[i][j];
            var += wv[i]*t;
        }
        double scl = (double)g1[o] / sqrt(var + 1e-5);
        g_l1sc[o] = (float)scl;
        g_l1sh[o] = (float)((double)bt1[o] - mean*scl);
    } else if (tid < 96) {
        int o = tid - 64;
        double wv[10];
        for (int i = 0; i < 10; i++) wv[i] = (double)w2[o*10 + i];
        double mean = (double)b2[o];
        for (int i = 0; i < 10; i++) mean += wv[i]*mm[i];
        double var = 0.0;
        for (int i = 0; i < 10; i++) {
            double t = 0.0;
            for (int j = 0; j < 10; j++) t += wv[j]*Cv[i][j];
            var += wv[i]*t;
        }
        double scl = (double)g2[o] / sqrt(var + 1e-5);
        g_l2sc[o] = (float)scl;
        g_l2sh[o] = (float)((double)bt2[o] - mean*scl);
    }
}

// ---------------- fused LSE (gather + 10->C MLP + BN + ReLU) + attentive pool ----------------
// feat half is constant over K: its score term cancels in softmax, and pooled
// feat channels == feat (handled downstream). Only sf channels computed here.
#define HPAD 20   // padded row length: float4-aligned, bank-conflict degree 4
template<int C>
__global__ void __launch_bounds__(C == 64 ? 128 : 256) lse_pool_kernel(
    const float* __restrict__ Wl,  const float* __restrict__ bl,
    const float* __restrict__ lsc, const float* __restrict__ lsh,
    const float* __restrict__ Wp,  float* __restrict__ pooled) {
    constexpr int WARPS = (C == 64) ? 4 : 8;
    constexpr int CPT   = C / 32;
    constexpr int NT    = WARPS * 32;
    __shared__ float wl_sh[10 * C];
    __shared__ float wp_sh[C * C];        // transposed: [c][o]
    __shared__ float prm_sh[3 * C];
    __shared__ __align__(16) float s_sh[WARPS][16][12];
    __shared__ __align__(16) float h_sh[WARPS][C][HPAD];   // [c][k], padded rows

    const int tid = threadIdx.x;
    for (int t = tid; t < 10*C; t += NT) { int i = t / C, c = t % C; wl_sh[t] = Wl[c*10 + i]; }
    for (int t = tid; t < C*C;  t += NT) { int c = t / C, o = t % C; wp_sh[t] = Wp[o*(2*C) + c]; }
    for (int t = tid; t < C;    t += NT) { prm_sh[t] = bl[t]; prm_sh[C+t] = lsc[t]; prm_sh[2*C+t] = lsh[t]; }
    __syncthreads();

    const int w = tid >> 5, lane = tid & 31;
    const int pt = blockIdx.x * WARPS + w;   // b*NN + n
    const int b  = pt >> 13;
    const int n  = pt & (NN-1);

    // phase 1: gather spatial features (k = lane for lane<16)
    if (lane < 16) {
        int gofs = (pt << 4) | lane;
        int j    = g_idx[gofs];
        float d  = g_dist[gofs];
        float4 ct = g_cpack[pt];
        float4 nb = g_cpack[(b << 13) + j];
        float* sr = s_sh[w][lane];
        sr[0]=ct.x; sr[1]=ct.y; sr[2]=ct.z;
        sr[3]=nb.x; sr[4]=nb.y; sr[5]=nb.z;
        sr[6]=ct.x-nb.x; sr[7]=ct.y-nb.y; sr[8]=ct.z-nb.z;
        sr[9]=d; sr[10]=0.f; sr[11]=0.f;
    }
    __syncwarp();

    // phase 2: 10->C MLP + BN + ReLU -> h_sh[c][k]
    {
        float wlr[CPT][10], br[CPT], scr[CPT], shr[CPT];
        #pragma unroll
        for (int cc = 0; cc < CPT; cc++) {
            int c = lane + 32*cc;
            #pragma unroll
            for (int i = 0; i < 10; i++) wlr[cc][i] = wl_sh[i*C + c];
            br[cc] = prm_sh[c]; scr[cc] = prm_sh[C + c]; shr[cc] = prm_sh[2*C + c];
        }
        #pragma unroll
        for (int k = 0; k < 16; k++) {
            const float4* sp = (const float4*)s_sh[w][k];
            float4 a0 = sp[0], a1 = sp[1], a2 = sp[2];
            float sv[10] = { a0.x,a0.y,a0.z,a0.w, a1.x,a1.y,a1.z,a1.w, a2.x,a2.y };
            #pragma unroll
            for (int cc = 0; cc < CPT; cc++) {
                float yv = br[cc];
                #pragma unroll
                for (int i = 0; i < 10; i++) yv = fmaf(wlr[cc][i], sv[i], yv);
                float v = fmaf(yv, scr[cc], shr[cc]);
                h_sh[w][lane + 32*cc][k] = fmaxf(v, 0.f);
            }
        }
    }
    __syncwarp();

    // phase 3: score GEMM  scores[o][k] = sum_c Wp[o,c] h[c][k]  (bias/feat cancel)
    float acc[CPT][16];
    #pragma unroll
    for (int cc = 0; cc < CPT; cc++)
        #pragma unroll
        for (int k = 0; k < 16; k++) acc[cc][k] = 0.f;

    #pragma unroll 4
    for (int c = 0; c < C; c++) {
        const float4* hp = (const float4*)&h_sh[w][c][0];
        float hv[16];
        *(float4*)&hv[0]  = hp[0]; *(float4*)&hv[4]  = hp[1];
        *(float4*)&hv[8]  = hp[2]; *(float4*)&hv[12] = hp[3];
        #pragma unroll
        for (int cc = 0; cc < CPT; cc++) {
            float wv = wp_sh[c*C + lane + 32*cc];
            #pragma unroll
            for (int k = 0; k < 16; k++) acc[cc][k] = fmaf(wv, hv[k], acc[cc][k]);
        }
    }

    // phase 4: softmax over K + weighted sum
    #pragma unroll
    for (int cc = 0; cc < CPT; cc++) {
        int o = lane + 32*cc;
        float m = acc[cc][0];
        #pragma unroll
        for (int k = 1; k < 16; k++) m = fmaxf(m, acc[cc][k]);
        float se = 0.f;
        #pragma unroll
        for (int k = 0; k < 16; k++) { acc[cc][k] = __expf(acc[cc][k] - m); se += acc[cc][k]; }
        const float4* hp = (const float4*)&h_sh[w][o][0];
        float hv[16];
        *(float4*)&hv[0]  = hp[0]; *(float4*)&hv[4]  = hp[1];
        *(float4*)&hv[8]  = hp[2]; *(float4*)&hv[12] = hp[3];
        float sum = 0.f;
        #pragma unroll
        for (int k = 0; k < 16; k++) sum = fmaf(acc[cc][k], hv[k], sum);
        pooled[((b*C + o) << 13) + n] = sum / se;
    }
}

// ---------------- final: BN + ReLU on mlp2 & res, concat write (leaky0.01 ∘ relu = relu) ----
__global__ void __launch_bounds__(256) final_kernel(float* __restrict__ out) {
    int t = (blockIdx.x << 8) + threadIdx.x;   // < BB*256*NN
    int b  = t >> 21;
    int r  = t & ((1 << 21) - 1);
    int ch = r >> 13;
    int n  = r & (NN-1);
    float v;
    if (ch < 128) v = fmaf(g_ymain[((b*128 + ch) << 13) + n], g_scm[ch], g_shm[ch]);
    else { int c = ch - 128; v = fmaf(g_yres[((b*128 + c) << 13) + n], g_scrs[c], g_shrs[c]); }
    out[t] = fmaxf(v, 0.f);
}

// ---------------- launch ----------------
extern "C" void kernel_launch(void* const* d_in, const int* in_sizes, int n_in,
                              void* d_out, int out_size) {
    const float* coords   = (const float*)d_in[0];
    const float* features = (const float*)d_in[1];
    const float* mlp1_w  = (const float*)d_in[2];
    const float* mlp1_b  = (const float*)d_in[3];
    const float* mlp1_g  = (const float*)d_in[4];
    const float* mlp1_bt = (const float*)d_in[5];
    const float* lse1_w  = (const float*)d_in[6];
    const float* lse1_b  = (const float*)d_in[7];
    const float* lse1_g  = (const float*)d_in[8];
    const float* lse1_bt = (const float*)d_in[9];
    const float* mlpp1_w  = (const float*)d_in[10];
    const float* mlpp1_b  = (const float*)d_in[11];
    const float* mlpp1_g  = (const float*)d_in[12];
    const float* mlpp1_bt = (const float*)d_in[13];
    const float* lse2_w  = (const float*)d_in[14];
    const float* lse2_b  = (const float*)d_in[15];
    const float* lse2_g  = (const float*)d_in[16];
    const float* lse2_bt = (const float*)d_in[17];
    const float* mlp2_w  = (const float*)d_in[18];
    const float* mlp2_b  = (const float*)d_in[19];
    const float* mlp2_g  = (const float*)d_in[20];
    const float* mlp2_bt = (const float*)d_in[21];
    const float* res_w  = (const float*)d_in[22];
    const float* res_b  = (const float*)d_in[23];
    const float* res_g  = (const float*)d_in[24];
    const float* res_bt = (const float*)d_in[25];
    const float* pool1_w = (const float*)d_in[26];
    // d_in[27] = pool1_b (cancels in softmax; pooled feat half is identity)
    const float* pool2_w = (const float*)d_in[28];
    // d_in[29] = pool2_b
    float* out = (float*)d_out;

    void *p_y1, *p_pool1, *p_y2, *p_pool2, *p_ymain, *p_yres;
    void *p_sc1, *p_sh1, *p_sc2, *p_sh2, *p_scm, *p_shm, *p_scrs, *p_shrs;
    void *p_l1sc, *p_l1sh, *p_l2sc, *p_l2sh;
    cudaGetSymbolAddress(&p_y1, g_y1);       cudaGetSymbolAddress(&p_pool1, g_pool1);
    cudaGetSymbolAddress(&p_y2, g_y2);       cudaGetSymbolAddress(&p_pool2, g_pool2);
    cudaGetSymbolAddress(&p_ymain, g_ymain); cudaGetSymbolAddress(&p_yres, g_yres);
    cudaGetSymbolAddress(&p_sc1, g_sc1);     cudaGetSymbolAddress(&p_sh1, g_sh1);
    cudaGetSymbolAddress(&p_sc2, g_sc2);     cudaGetSymbolAddress(&p_sh2, g_sh2);
    cudaGetSymbolAddress(&p_scm, g_scm);     cudaGetSymbolAddress(&p_shm, g_shm);
    cudaGetSymbolAddress(&p_scrs, g_scrs);   cudaGetSymbolAddress(&p_shrs, g_shrs);
    cudaGetSymbolAddress(&p_l1sc, g_l1sc);   cudaGetSymbolAddress(&p_l1sh, g_l1sh);
    cudaGetSymbolAddress(&p_l2sc, g_l2sc);   cudaGetSymbolAddress(&p_l2sh, g_l2sh);

    // geometry (also zeros BN accumulators)
    pack_kernel<<<64, 256>>>(coords);
    knn_kernel<<<2048, 256>>>();
    moments_kernel<<<256, 256>>>();
    finalize_lse_kernel<<<1, 1024>>>(lse1_w, lse1_b, lse1_g, lse1_bt,
                                     lse2_w, lse2_b, lse2_g, lse2_bt);

    // mlp1: features(32) -> 64, stats fused
    conv1x1_kernel<32,32,false><<<dim3(64,2), 256>>>(features, nullptr, mlp1_w, mlp1_b,
                                                     nullptr, nullptr, 0.f, (float*)p_y1, 64, 0);
    bnfin_kernel<<<1, 64>>>(0, 64, mlp1_g, mlp1_bt, (float*)p_sc1, (float*)p_sh1);

    // lse1 + pool1 (sf half only)
    lse_pool_kernel<64><<<4096, 128>>>(lse1_w, lse1_b, (float*)p_l1sc, (float*)p_l1sh,
                                       pool1_w, (float*)p_pool1);

    // mlpp1: [pool1_sf(64); bn+leaky0.2(y1)(64)] -> 32, stats fused
    conv1x1_kernel<128,64,true><<<dim3(64,1), 256>>>((float*)p_pool1, (float*)p_y1, mlpp1_w, mlpp1_b,
                                                     (float*)p_sc1, (float*)p_sh1, 0.2f, (float*)p_y2, 32, 64);
    bnfin_kernel<<<1, 32>>>(64, 32, mlpp1_g, mlpp1_bt, (float*)p_sc2, (float*)p_sh2);

    // lse2 + pool2
    lse_pool_kernel<32><<<2048, 256>>>(lse2_w, lse2_b, (float*)p_l2sc, (float*)p_l2sh,
                                       pool2_w, (float*)p_pool2);

    // mlp2: [pool2_sf(32); bn+relu(y2)(32)] -> 128, stats fused
    conv1x1_kernel<64,32,true><<<dim3(64,4), 256>>>((float*)p_pool2, (float*)p_y2, mlp2_w, mlp2_b,
                                                    (float*)p_sc2, (float*)p_sh2, 0.0f, (float*)p_ymain, 128, 96);
    // residual: features(32) -> 128, stats fused
    conv1x1_kernel<32,32,false><<<dim3(64,4), 256>>>(features, nullptr, res_w, res_b,
                                                     nullptr, nullptr, 0.f, (float*)p_yres, 128, 224);
    bnfin_kernel<<<1, 128>>>(96, 128, mlp2_g, mlp2_bt, (float*)p_scm, (float*)p_shm);
    bnfin_kernel<<<1, 128>>>(224, 128, res_g, res_bt, (float*)p_scrs, (float*)p_shrs);

    // fused BN + ReLU + concat (+ identity leaky 0.01)
    final_kernel<<<16384, 256>>>(out);
}

// round 4
// speedup vs baseline: 1.2289x; 1.0893x over previous
#include <cuda_runtime.h>
#include <math.h>
#include <stdint.h>

#define BB 2
#define NN 8192
#define KK 16

// ---------------- scratch (static device globals; no allocation) ----------------
__device__ __align__(16) float4 g_cpack[BB*NN];
__device__ __align__(16) int    g_idx [BB*NN*KK];
__device__ __align__(16) float  g_dist[BB*NN*KK];
__device__ __align__(16) float  g_y1   [BB*64 *NN];   // mlp1 raw conv out
__device__ __align__(16) float  g_pool1[BB*64 *NN];   // attentive pool1, sf half
__device__ __align__(16) float  g_y2   [BB*32 *NN];   // mlpp1 raw conv out
__device__ __align__(16) float  g_pool2[BB*32 *NN];   // attentive pool2, sf half
__device__ __align__(16) float  g_ymain[BB*128*NN];   // mlp2 raw
__device__ __align__(16) float  g_yres [BB*128*NN];   // res raw
__device__ double g_msum[65];           // spatial moments (global accumulation)
__device__ double g_csum [352];         // fused BN sums: [0,64)=mlp1 [64,96)=mlpp1 [96,224)=mlp2 [224,352)=res
__device__ double g_csum2[352];
__device__ float  g_sc1[64],  g_sh1[64];
__device__ float  g_sc2[32],  g_sh2[32];
__device__ float  g_scm[128], g_shm[128];
__device__ float  g_scrs[128],g_shrs[128];
__device__ float  g_l1sc[64], g_l1sh[64];
__device__ float  g_l2sc[32], g_l2sh[32];

// ---------------- pack coords + squared norm; zero accumulators ----------------
__global__ void __launch_bounds__(256) pack_kernel(const float* __restrict__ coords) {
    int p = (blockIdx.x << 8) + threadIdx.x;          // < BB*NN
    float x = coords[p*3+0], y = coords[p*3+1], z = coords[p*3+2];
    g_cpack[p] = make_float4(x, y, z, fmaf(x, x, fmaf(y, y, z*z)));
    if (p < 352) { g_csum[p] = 0.0; g_csum2[p] = 0.0; }
    if (p < 65)  g_msum[p] = 0.0;
}

// ---------------- KNN: warp per query, thresholded depth-8 buffer select ----------------
__device__ __forceinline__ void warp_merge8(float* md, int* mi,
                                            float* topd, int* topi,
                                            int lane, int& cnt, float& tau) {
    const float INF = __int_as_float(0x7f800000);
    for (int s = cnt; s < 8; s++) md[lane*8 + s] = INF;
    if (lane < 16) { md[256 + lane] = topd[lane]; mi[256 + lane] = topi[lane]; }
    __syncwarp();
    #pragma unroll 1
    for (int r = 0; r < 16; r++) {
        float v = md[lane]; int p = lane;
        #pragma unroll
        for (int e = 1; e < 9; e++) {
            int q = lane + e*32;          // e=8 touches [256,288): top + INF pad
            float x = md[q];
            if (x < v) { v = x; p = q; }
        }
        #pragma unroll
        for (int off = 16; off; off >>= 1) {
            float v2 = __shfl_xor_sync(0xffffffffu, v, off);
            int   p2 = __shfl_xor_sync(0xffffffffu, p, off);
            if (v2 < v || (v2 == v && p2 < p)) { v = v2; p = p2; }
        }
        if (lane == 0) { topd[r] = v; topi[r] = mi[p]; md[p] = INF; }
        __syncwarp();
    }
    cnt = 0;
    tau = topd[15];
    __syncwarp();
}

__global__ void __launch_bounds__(512) knn_kernel() {
    extern __shared__ char dyn[];
    float4* tile = (float4*)dyn;                           // 2048*16   = 32768
    float*  smd  = (float*)(dyn + 32768);                  // 16*288*4  = 18432
    int*    smi  = (int*)  (dyn + 32768 + 18432);          // 18432
    float*  std_ = (float*)(dyn + 69632);                  // 16*16*4   = 1024
    int*    sti  = (int*)  (dyn + 70656);                  // 1024

    const float INF = __int_as_float(0x7f800000);
    const int tid = threadIdx.x, w = tid >> 5, lane = tid & 31;
    const int b   = blockIdx.x >> 9;                       // 512 blocks per batch
    const int n   = ((blockIdx.x & 511) << 4) | w;         // 16 queries/block

    float* md   = smd  + w*288;  int* mi   = smi + w*288;
    float* topd = std_ + w*16;   int* topi = sti + w*16;

    if (lane < 16) { topd[lane] = INF; topi[lane] = 0; md[272 + lane] = INF; }
    const float4 ci = g_cpack[(b << 13) + n];
    float tau = INF;
    int cnt = 0;
    __syncwarp();

    for (int t = 0; t < 4; t++) {
        __syncthreads();
        for (int q = tid; q < 2048; q += 512)
            tile[q] = g_cpack[(b << 13) + (t << 11) + q];
        __syncthreads();
        #pragma unroll 1
        for (int g = 0; g < 2048; g += 128) {
            float4 c0 = tile[g + lane];
            float4 c1 = tile[g + lane + 32];
            float4 c2 = tile[g + lane + 64];
            float4 c3 = tile[g + lane + 96];
            int j0 = (t << 11) + g + lane;
            float d0 = fmaf(-2.f, fmaf(ci.x,c0.x, fmaf(ci.y,c0.y, ci.z*c0.z)), ci.w + c0.w);
            float d1 = fmaf(-2.f, fmaf(ci.x,c1.x, fmaf(ci.y,c1.y, ci.z*c1.z)), ci.w + c1.w);
            float d2 = fmaf(-2.f, fmaf(ci.x,c2.x, fmaf(ci.y,c2.y, ci.z*c2.z)), ci.w + c2.w);
            float d3 = fmaf(-2.f, fmaf(ci.x,c3.x, fmaf(ci.y,c3.y, ci.z*c3.z)), ci.w + c3.w);
            if (d0 < tau && j0      != n) { md[lane*8+cnt] = d0; mi[lane*8+cnt] = j0;      cnt++; }
            if (d1 < tau && j0+32   != n) { md[lane*8+cnt] = d1; mi[lane*8+cnt] = j0+32;   cnt++; }
            if (d2 < tau && j0+64   != n) { md[lane*8+cnt] = d2; mi[lane*8+cnt] = j0+64;   cnt++; }
            if (d3 < tau && j0+96   != n) { md[lane*8+cnt] = d3; mi[lane*8+cnt] = j0+96;   cnt++; }
            if (__ballot_sync(0xffffffffu, cnt > 4))
                warp_merge8(md, mi, topd, topi, lane, cnt, tau);
        }
    }
    warp_merge8(md, mi, topd, topi, lane, cnt, tau);
    if (lane < 16) {
        int gofs = ((((b << 13) | n)) << 4) | lane;
        g_idx [gofs] = topi[lane];
        g_dist[gofs] = fmaxf(topd[lane], 0.0f);
    }
}

// ---------------- 1x1 conv (channel GEMM), 32 outputs/thread, fused BN-stat reduce ----------
template<int CI, int CI0, bool ACT1>
__global__ void __launch_bounds__(256) conv1x1_kernel(
    const float* __restrict__ in0, const float* __restrict__ in1,
    const float* __restrict__ W,   const float* __restrict__ bias,
    const float* __restrict__ sc1, const float* __restrict__ sh1, float slope,
    float* __restrict__ y, int CO, int acc_off) {
    __shared__ float Wsh[CI*32];
    __shared__ float bsh[32];
    __shared__ float scsh[ACT1 ? (CI-CI0) : 1], shsh[ACT1 ? (CI-CI0) : 1];
    __shared__ float red_s[8][32], red_q[8][32];
    const int oc0 = blockIdx.y << 5;
    for (int t = threadIdx.x; t < CI*32; t += 256) {
        int i = t >> 5, ol = t & 31;
        Wsh[t] = W[(oc0 + ol)*CI + i];
    }
    if (threadIdx.x < 32) bsh[threadIdx.x] = bias[oc0 + threadIdx.x];
    if (ACT1 && threadIdx.x < (CI-CI0)) {
        scsh[threadIdx.x] = sc1[threadIdx.x];
        shsh[threadIdx.x] = sh1[threadIdx.x];
    }
    __syncthreads();
    const int p = (blockIdx.x << 8) + threadIdx.x;   // < BB*NN
    const int b = p >> 13, n = p & (NN-1);
    const int w = threadIdx.x >> 5, lane = threadIdx.x & 31;
    float acc[32];
    #pragma unroll
    for (int o = 0; o < 32; o++) acc[o] = bsh[o];
    #pragma unroll 4
    for (int i = 0; i < CI0; i++) {
        float x = in0[((b*CI0 + i) << 13) + n];
        #pragma unroll
        for (int o = 0; o < 32; o++) acc[o] = fmaf(Wsh[(i << 5) + o], x, acc[o]);
    }
    if (CI > CI0) {
        #pragma unroll 4
        for (int i = 0; i < CI - CI0; i++) {
            float x = in1[((b*(CI-CI0) + i) << 13) + n];
            if (ACT1) {
                x = fmaf(x, scsh[i], shsh[i]);
                x = x > 0.f ? x : slope * x;
            }
            #pragma unroll
            for (int o = 0; o < 32; o++) acc[o] = fmaf(Wsh[((CI0 + i) << 5) + o], x, acc[o]);
        }
    }
    #pragma unroll
    for (int o = 0; o < 32; o++)
        y[((b*CO + oc0 + o) << 13) + n] = acc[o];

    // fused per-channel sum / sumsq reduction
    #pragma unroll
    for (int o = 0; o < 32; o++) {
        float v = acc[o];
        float q = v * v;
        #pragma unroll
        for (int off = 16; off; off >>= 1) {
            v += __shfl_xor_sync(0xffffffffu, v, off);
            q += __shfl_xor_sync(0xffffffffu, q, off);
        }
        if (lane == 0) { red_s[w][o] = v; red_q[w][o] = q; }
    }
    __syncthreads();
    if (threadIdx.x < 64) {
        int o = threadIdx.x & 31, which = threadIdx.x >> 5;
        float s = 0.f;
        #pragma unroll
        for (int ww = 0; ww < 8; ww++) s += which ? red_q[ww][o] : red_s[ww][o];
        atomicAdd(which ? &g_csum2[acc_off + oc0 + o] : &g_csum[acc_off + oc0 + o], (double)s);
    }
}

// ---------------- finalize BN params from fused sums ----------------
__global__ void bnfin_kernel(int off, int CO,
                             const float* __restrict__ g, const float* __restrict__ bt,
                             float* __restrict__ scale, float* __restrict__ shift) {
    int o = threadIdx.x;
    if (o >= CO) return;
    const double P = (double)(BB*NN);
    double mean = g_csum[off + o] / P;
    double var  = g_csum2[off + o] / P - mean*mean;
    double scl  = (double)g[o] / sqrt(var + 1e-5);
    scale[o] = (float)scl;
    shift[o] = (float)((double)bt[o] - mean*scl);
}

// two sets at once (mlp2 @96, res @224)
__global__ void bnfin2_kernel(const float* __restrict__ g1, const float* __restrict__ bt1,
                              float* __restrict__ sc1, float* __restrict__ sh1,
                              const float* __restrict__ g2, const float* __restrict__ bt2,
                              float* __restrict__ sc2, float* __restrict__ sh2) {
    int t = threadIdx.x;
    const double P = (double)(BB*NN);
    int off = (t < 128) ? 96 : 224;
    int o   = t & 127;
    double mean = g_csum[off + o] / P;
    double var  = g_csum2[off + o] / P - mean*mean;
    const float* gg = (t < 128) ? g1 : g2;
    const float* bb = (t < 128) ? bt1 : bt2;
    double scl = (double)gg[o] / sqrt(var + 1e-5);
    if (t < 128) { sc1[o] = (float)scl; sh1[o] = (float)((double)bb[o] - mean*scl); }
    else         { sc2[o] = (float)scl; sh2[o] = (float)((double)bb[o] - mean*scl); }
}

// ---------------- spatial moments (shared by lse1 & lse2 BN), global accumulate -----------
__global__ void __launch_bounds__(256) moments_kernel() {
    const int tid = threadIdx.x;
    float a[65];
    #pragma unroll
    for (int v = 0; v < 65; v++) a[v] = 0.f;
    const int p0 = (((blockIdx.x << 8) + tid) << 2);
    for (int q = 0; q < 4; q++) {
        int p  = p0 + q;
        int bn = p >> 4;
        int b  = bn >> 13;
        int j  = g_idx[p];
        float d = g_dist[p];
        float4 ct = g_cpack[bn];
        float4 nb = g_cpack[(b << 13) + j];
        float s[10] = { ct.x, ct.y, ct.z, nb.x, nb.y, nb.z,
                        ct.x-nb.x, ct.y-nb.y, ct.z-nb.z, d };
        int c2 = 10;
        #pragma unroll
        for (int i = 0; i < 10; i++) {
            a[i] += s[i];
            #pragma unroll
            for (int j2 = i; j2 < 10; j2++) { a[c2] = fmaf(s[i], s[j2], a[c2]); c2++; }
        }
    }
    __shared__ double sacc[65];
    if (tid < 65) sacc[tid] = 0.0;
    __syncthreads();
    #pragma unroll
    for (int v = 0; v < 65; v++) {
        float x = a[v];
        #pragma unroll
        for (int off = 16; off; off >>= 1) x += __shfl_down_sync(0xffffffffu, x, off);
        if ((tid & 31) == 0) atomicAdd(&sacc[v], (double)x);
    }
    __syncthreads();
    if (tid < 65) atomicAdd(&g_msum[tid], sacc[tid]);
}

// ---------------- finalize lse BN params: mean = w·m + b, var = w^T C w -------------------
__global__ void __launch_bounds__(128) finalize_lse_kernel(
    const float* __restrict__ w1, const float* __restrict__ b1,
    const float* __restrict__ g1, const float* __restrict__ bt1,
    const float* __restrict__ w2, const float* __restrict__ b2,
    const float* __restrict__ g2, const float* __restrict__ bt2) {
    __shared__ double M[65];
    __shared__ double mm[10];
    __shared__ double Cv[10][10];
    const int tid = threadIdx.x;
    if (tid < 65) M[tid] = g_msum[tid];
    __syncthreads();
    const double P = (double)BB * NN * KK;
    if (tid < 10) mm[tid] = M[tid] / P;
    __syncthreads();
    if (tid < 100) {
        int i = tid/10, j = tid%10;
        if (j >= i) {
            int off = 10 + i*10 - (i*(i-1))/2 + (j - i);
            double c = M[off]/P - mm[i]*mm[j];
            Cv[i][j] = c; Cv[j][i] = c;
        }
    }
    __syncthreads();
    if (tid < 64) {
        int o = tid;
        double wv[10];
        for (int i = 0; i < 10; i++) wv[i] = (double)w1[o*10 + i];
        double mean = (double)b1[o];
        for (int i = 0; i < 10; i++) mean += wv[i]*mm[i];
        double var = 0.0;
        for (int i = 0; i < 10; i++) {
            double t = 0.0;
            for (int j = 0; j < 10; j++) t += wv[j]*Cv[i][j];
            var += wv[i]*t;
        }
        double scl = (double)g1[o] / sqrt(var + 1e-5);
        g_l1sc[o] = (float)scl;
        g_l1sh[o] = (float)((double)bt1[o] - mean*scl);
    }
    if (tid >= 64 && tid < 96) {
        int o = tid - 64;
        double wv[10];
        for (int i = 0; i < 10; i++) wv[i] = (double)w2[o*10 + i];
        double mean = (double)b2[o];
        for (int i = 0; i < 10; i++) mean += wv[i]*mm[i];
        double var = 0.0;
        for (int i = 0; i < 10; i++) {
            double t = 0.0;
            for (int j = 0; j < 10; j++) t += wv[j]*Cv[i][j];
            var += wv[i]*t;
        }
        double scl = (double)g2[o] / sqrt(var + 1e-5);
        g_l2sc[o] = (float)scl;
        g_l2sh[o] = (float)((double)bt2[o] - mean*scl);
    }
}

// ---------------- fused LSE (gather + 10->C MLP + BN + ReLU) + attentive pool ----------------
// feat half is constant over K: its score term cancels in softmax, and pooled
// feat channels == feat (handled downstream). Only sf channels computed here.
#define HPAD 20   // padded row length: float4-aligned, bank-conflict degree 4
template<int C>
__global__ void __launch_bounds__(C == 64 ? 128 : 256) lse_pool_kernel(
    const float* __restrict__ Wl,  const float* __restrict__ bl,
    const float* __restrict__ lsc, const float* __restrict__ lsh,
    const float* __restrict__ Wp,  float* __restrict__ pooled) {
    constexpr int WARPS = (C == 64) ? 4 : 8;
    constexpr int CPT   = C / 32;
    constexpr int NT    = WARPS * 32;
    __shared__ float wl_sh[10 * C];
    __shared__ float wp_sh[C * C];        // transposed: [c][o]
    __shared__ float prm_sh[3 * C];
    __shared__ __align__(16) float s_sh[WARPS][16][12];
    __shared__ __align__(16) float h_sh[WARPS][C][HPAD];   // [c][k], padded rows

    const int tid = threadIdx.x;
    for (int t = tid; t < 10*C; t += NT) { int i = t / C, c = t % C; wl_sh[t] = Wl[c*10 + i]; }
    for (int t = tid; t < C*C;  t += NT) { int c = t / C, o = t % C; wp_sh[t] = Wp[o*(2*C) + c]; }
    for (int t = tid; t < C;    t += NT) { prm_sh[t] = bl[t]; prm_sh[C+t] = lsc[t]; prm_sh[2*C+t] = lsh[t]; }
    __syncthreads();

    const int w = tid >> 5, lane = tid & 31;
    const int pt = blockIdx.x * WARPS + w;   // b*NN + n
    const int b  = pt >> 13;
    const int n  = pt & (NN-1);

    // phase 1: gather spatial features (k = lane for lane<16)
    if (lane < 16) {
        int gofs = (pt << 4) | lane;
        int j    = g_idx[gofs];
        float d  = g_dist[gofs];
        float4 ct = g_cpack[pt];
        float4 nb = g_cpack[(b << 13) + j];
        float* sr = s_sh[w][lane];
        sr[0]=ct.x; sr[1]=ct.y; sr[2]=ct.z;
        sr[3]=nb.x; sr[4]=nb.y; sr[5]=nb.z;
        sr[6]=ct.x-nb.x; sr[7]=ct.y-nb.y; sr[8]=ct.z-nb.z;
        sr[9]=d; sr[10]=0.f; sr[11]=0.f;
    }
    __syncwarp();

    // phase 2: 10->C MLP + BN + ReLU -> h_sh[c][k]
    {
        float wlr[CPT][10], br[CPT], scr[CPT], shr[CPT];
        #pragma unroll
        for (int cc = 0; cc < CPT; cc++) {
            int c = lane + 32*cc;
            #pragma unroll
            for (int i = 0; i < 10; i++) wlr[cc][i] = wl_sh[i*C + c];
            br[cc] = prm_sh[c]; scr[cc] = prm_sh[C + c]; shr[cc] = prm_sh[2*C + c];
        }
        #pragma unroll
        for (int k = 0; k < 16; k++) {
            const float4* sp = (const float4*)s_sh[w][k];
            float4 a0 = sp[0], a1 = sp[1], a2 = sp[2];
            float sv[10] = { a0.x,a0.y,a0.z,a0.w, a1.x,a1.y,a1.z,a1.w, a2.x,a2.y };
            #pragma unroll
            for (int cc = 0; cc < CPT; cc++) {
                float yv = br[cc];
                #pragma unroll
                for (int i = 0; i < 10; i++) yv = fmaf(wlr[cc][i], sv[i], yv);
                float v = fmaf(yv, scr[cc], shr[cc]);
                h_sh[w][lane + 32*cc][k] = fmaxf(v, 0.f);
            }
        }
    }
    __syncwarp();

    // phase 3: score GEMM  scores[o][k] = sum_c Wp[o,c] h[c][k]  (bias/feat cancel)
    float acc[CPT][16];
    #pragma unroll
    for (int cc = 0; cc < CPT; cc++)
        #pragma unroll
        for (int k = 0; k < 16; k++) acc[cc][k] = 0.f;

    #pragma unroll 4
    for (int c = 0; c < C; c++) {
        const float4* hp = (const float4*)&h_sh[w][c][0];
        float hv[16];
        *(float4*)&hv[0]  = hp[0]; *(float4*)&hv[4]  = hp[1];
        *(float4*)&hv[8]  = hp[2]; *(float4*)&hv[12] = hp[3];
        #pragma unroll
        for (int cc = 0; cc < CPT; cc++) {
            float wv = wp_sh[c*C + lane + 32*cc];
            #pragma unroll
            for (int k = 0; k < 16; k++) acc[cc][k] = fmaf(wv, hv[k], acc[cc][k]);
        }
    }

    // phase 4: softmax over K + weighted sum
    #pragma unroll
    for (int cc = 0; cc < CPT; cc++) {
        int o = lane + 32*cc;
        float m = acc[cc][0];
        #pragma unroll
        for (int k = 1; k < 16; k++) m = fmaxf(m, acc[cc][k]);
        float se = 0.f;
        #pragma unroll
        for (int k = 0; k < 16; k++) { acc[cc][k] = __expf(acc[cc][k] - m); se += acc[cc][k]; }
        const float4* hp = (const float4*)&h_sh[w][o][0];
        float hv[16];
        *(float4*)&hv[0]  = hp[0]; *(float4*)&hv[4]  = hp[1];
        *(float4*)&hv[8]  = hp[2]; *(float4*)&hv[12] = hp[3];
        float sum = 0.f;
        #pragma unroll
        for (int k = 0; k < 16; k++) sum = fmaf(acc[cc][k], hv[k], sum);
        pooled[((b*C + o) << 13) + n] = sum / se;
    }
}

// ---------------- final: BN + ReLU on mlp2 & res, concat write, float4 -------------------
__global__ void __launch_bounds__(256) final_kernel(float4* __restrict__ out) {
    int t = (blockIdx.x << 8) + threadIdx.x;     // < BB*256*NN/4
    int base = t << 2;
    int b  = base >> 21;
    int r  = base & ((1 << 21) - 1);
    int ch = r >> 13;
    int n  = r & (NN-1);
    float4 v;
    float sc, sh;
    if (ch < 128) {
        v = *(const float4*)&g_ymain[((b*128 + ch) << 13) + n];
        sc = g_scm[ch]; sh = g_shm[ch];
    } else {
        int c = ch - 128;
        v = *(const float4*)&g_yres[((b*128 + c) << 13) + n];
        sc = g_scrs[c]; sh = g_shrs[c];
    }
    v.x = fmaxf(fmaf(v.x, sc, sh), 0.f);
    v.y = fmaxf(fmaf(v.y, sc, sh), 0.f);
    v.z = fmaxf(fmaf(v.z, sc, sh), 0.f);
    v.w = fmaxf(fmaf(v.w, sc, sh), 0.f);
    out[t] = v;
}

// ---------------- launch ----------------
extern "C" void kernel_launch(void* const* d_in, const int* in_sizes, int n_in,
                              void* d_out, int out_size) {
    const float* coords   = (const float*)d_in[0];
    const float* features = (const float*)d_in[1];
    const float* mlp1_w  = (const float*)d_in[2];
    const float* mlp1_b  = (const float*)d_in[3];
    const float* mlp1_g  = (const float*)d_in[4];
    const float* mlp1_bt = (const float*)d_in[5];
    const float* lse1_w  = (const float*)d_in[6];
    const float* lse1_b  = (const float*)d_in[7];
    const float* lse1_g  = (const float*)d_in[8];
    const float* lse1_bt = (const float*)d_in[9];
    const float* mlpp1_w  = (const float*)d_in[10];
    const float* mlpp1_b  = (const float*)d_in[11];
    const float* mlpp1_g  = (const float*)d_in[12];
    const float* mlpp1_bt = (const float*)d_in[13];
    const float* lse2_w  = (const float*)d_in[14];
    const float* lse2_b  = (const float*)d_in[15];
    const float* lse2_g  = (const float*)d_in[16];
    const float* lse2_bt = (const float*)d_in[17];
    const float* mlp2_w  = (const float*)d_in[18];
    const float* mlp2_b  = (const float*)d_in[19];
    const float* mlp2_g  = (const float*)d_in[20];
    const float* mlp2_bt = (const float*)d_in[21];
    const float* res_w  = (const float*)d_in[22];
    const float* res_b  = (const float*)d_in[23];
    const float* res_g  = (const float*)d_in[24];
    const float* res_bt = (const float*)d_in[25];
    const float* pool1_w = (const float*)d_in[26];
    // d_in[27] = pool1_b (cancels in softmax; pooled feat half is identity)
    const float* pool2_w = (const float*)d_in[28];
    // d_in[29] = pool2_b
    float* out = (float*)d_out;

    void *p_y1, *p_pool1, *p_y2, *p_pool2, *p_ymain, *p_yres;
    void *p_sc1, *p_sh1, *p_sc2, *p_sh2, *p_scm, *p_shm, *p_scrs, *p_shrs;
    void *p_l1sc, *p_l1sh, *p_l2sc, *p_l2sh;
    cudaGetSymbolAddress(&p_y1, g_y1);       cudaGetSymbolAddress(&p_pool1, g_pool1);
    cudaGetSymbolAddress(&p_y2, g_y2);       cudaGetSymbolAddress(&p_pool2, g_pool2);
    cudaGetSymbolAddress(&p_ymain, g_ymain); cudaGetSymbolAddress(&p_yres, g_yres);
    cudaGetSymbolAddress(&p_sc1, g_sc1);     cudaGetSymbolAddress(&p_sh1, g_sh1);
    cudaGetSymbolAddress(&p_sc2, g_sc2);     cudaGetSymbolAddress(&p_sh2, g_sh2);
    cudaGetSymbolAddress(&p_scm, g_scm);     cudaGetSymbolAddress(&p_shm, g_shm);
    cudaGetSymbolAddress(&p_scrs, g_scrs);   cudaGetSymbolAddress(&p_shrs, g_shrs);
    cudaGetSymbolAddress(&p_l1sc, g_l1sc);   cudaGetSymbolAddress(&p_l1sh, g_l1sh);
    cudaGetSymbolAddress(&p_l2sc, g_l2sc);   cudaGetSymbolAddress(&p_l2sh, g_l2sh);

    static bool attr_done = false;
    if (!attr_done) {
        cudaFuncSetAttribute(knn_kernel, cudaFuncAttributeMaxDynamicSharedMemorySize, 71680);
        attr_done = true;
    }

    // geometry (also zeros accumulators)
    pack_kernel<<<64, 256>>>(coords);
    knn_kernel<<<1024, 512, 71680>>>();
    moments_kernel<<<256, 256>>>();
    finalize_lse_kernel<<<1, 128>>>(lse1_w, lse1_b, lse1_g, lse1_bt,
                                    lse2_w, lse2_b, lse2_g, lse2_bt);

    // mlp1: features(32) -> 64, stats fused
    conv1x1_kernel<32,32,false><<<dim3(64,2), 256>>>(features, nullptr, mlp1_w, mlp1_b,
                                                     nullptr, nullptr, 0.f, (float*)p_y1, 64, 0);
    bnfin_kernel<<<1, 64>>>(0, 64, mlp1_g, mlp1_bt, (float*)p_sc1, (float*)p_sh1);

    // lse1 + pool1 (sf half only)
    lse_pool_kernel<64><<<4096, 128>>>(lse1_w, lse1_b, (float*)p_l1sc, (float*)p_l1sh,
                                       pool1_w, (float*)p_pool1);

    // mlpp1: [pool1_sf(64); bn+leaky0.2(y1)(64)] -> 32, stats fused
    conv1x1_kernel<128,64,true><<<dim3(64,1), 256>>>((float*)p_pool1, (float*)p_y1, mlpp1_w, mlpp1_b,
                                                     (float*)p_sc1, (float*)p_sh1, 0.2f, (float*)p_y2, 32, 64);
    bnfin_kernel<<<1, 32>>>(64, 32, mlpp1_g, mlpp1_bt, (float*)p_sc2, (float*)p_sh2);

    // lse2 + pool2
    lse_pool_kernel<32><<<2048, 256>>>(lse2_w, lse2_b, (float*)p_l2sc, (float*)p_l2sh,
                                       pool2_w, (float*)p_pool2);

    // mlp2: [pool2_sf(32); bn+relu(y2)(32)] -> 128, stats fused
    conv1x1_kernel<64,32,true><<<dim3(64,4), 256>>>((float*)p_pool2, (float*)p_y2, mlp2_w, mlp2_b,
                                                    (float*)p_sc2, (float*)p_sh2, 0.0f, (float*)p_ymain, 128, 96);
    // residual: features(32) -> 128, stats fused
    conv1x1_kernel<32,32,false><<<dim3(64,4), 256>>>(features, nullptr, res_w, res_b,
                                                     nullptr, nullptr, 0.f, (float*)p_yres, 128, 224);
    bnfin2_kernel<<<1, 256>>>(mlp2_g, mlp2_bt, (float*)p_scm, (float*)p_shm,
                              res_g, res_bt, (float*)p_scrs, (float*)p_shrs);

    // fused BN + ReLU + concat (+ identity leaky 0.01), float4
    final_kernel<<<4096, 256>>>((float4*)out);
}

// round 5
// speedup vs baseline: 1.2314x; 1.0020x over previous
#include <cuda_runtime.h>
#include <math.h>
#include <stdint.h>

#define BB 2
#define NN 8192
#define KK 16

// ---------------- f32x2 packed-math helpers (sm_100+ PTX) ----------------
__device__ __forceinline__ unsigned long long ffma2(unsigned long long a, unsigned long long b,
                                                    unsigned long long c) {
    unsigned long long d;
    asm("fma.rn.f32x2 %0, %1, %2, %3;" : "=l"(d) : "l"(a), "l"(b), "l"(c));
    return d;
}
__device__ __forceinline__ unsigned long long pack2(float x, float y) {
    unsigned long long d;
    asm("mov.b64 %0, {%1, %2};" : "=l"(d) : "f"(x), "f"(y));
    return d;
}
__device__ __forceinline__ float2 unpack2(unsigned long long v) {
    float2 r;
    asm("mov.b64 {%0, %1}, %2;" : "=f"(r.x), "=f"(r.y) : "l"(v));
    return r;
}

// ---------------- scratch (static device globals; no allocation) ----------------
__device__ __align__(16) float4 g_cpack[BB*NN];   // raw coords + |c|^2
__device__ __align__(16) float4 g_cneg [BB*NN];   // (-2x,-2y,-2z, |c|^2) for KNN
__device__ __align__(16) int    g_idx [BB*NN*KK];
__device__ __align__(16) float  g_dist[BB*NN*KK];
__device__ __align__(16) float  g_y1   [BB*64 *NN];
__device__ __align__(16) float  g_pool1[BB*64 *NN];
__device__ __align__(16) float  g_y2   [BB*32 *NN];
__device__ __align__(16) float  g_pool2[BB*32 *NN];
__device__ __align__(16) float  g_ymain[BB*128*NN];
__device__ __align__(16) float  g_yres [BB*128*NN];
__device__ double g_msum[65];
__device__ double g_csum [352];   // [0,64)=mlp1 [64,96)=mlpp1 [96,224)=mlp2 [224,352)=res
__device__ double g_csum2[352];
__device__ float  g_sc1[64],  g_sh1[64];
__device__ float  g_sc2[32],  g_sh2[32];
__device__ float  g_scm[128], g_shm[128];
__device__ float  g_scrs[128],g_shrs[128];
__device__ float  g_l1sc[64], g_l1sh[64];
__device__ float  g_l2sc[32], g_l2sh[32];

// ---------------- pack coords + squared norm; zero accumulators ----------------
__global__ void __launch_bounds__(256) pack_kernel(const float* __restrict__ coords) {
    int p = (blockIdx.x << 8) + threadIdx.x;          // < BB*NN
    float x = coords[p*3+0], y = coords[p*3+1], z = coords[p*3+2];
    float w = fmaf(x, x, fmaf(y, y, z*z));
    g_cpack[p] = make_float4(x, y, z, w);
    g_cneg[p]  = make_float4(-2.f*x, -2.f*y, -2.f*z, w);
    if (p < 352) { g_csum[p] = 0.0; g_csum2[p] = 0.0; }
    if (p < 65)  g_msum[p] = 0.0;
}

// ---------------- KNN: warp/query, depth-12 stride-13 buffer, trigger cnt>8 ----------------
// buffer layout per warp: md/mi[448]: buffer md[lane*13+s] s<13 (covers [0,416)),
// top copy at [416,432), INF pad at [432,448). merge scans rows md[lane + e*32], e<14.
__device__ __forceinline__ void warp_merge12(float* md, int* mi,
                                             float* topd, int* topi,
                                             int lane, int& cnt, float& tau) {
    const float INF = __int_as_float(0x7f800000);
    for (int s = cnt; s < 13; s++) md[lane*13 + s] = INF;
    if (lane < 16) { md[416 + lane] = topd[lane]; mi[416 + lane] = topi[lane]; }
    __syncwarp();
    #pragma unroll 1
    for (int r = 0; r < 16; r++) {
        float v = md[lane]; int p = lane;
        #pragma unroll
        for (int e = 1; e < 14; e++) {
            int q = lane + e*32;
            float x = md[q];
            if (x < v) { v = x; p = q; }
        }
        #pragma unroll
        for (int off = 16; off; off >>= 1) {
            float v2 = __shfl_xor_sync(0xffffffffu, v, off);
            int   p2 = __shfl_xor_sync(0xffffffffu, p, off);
            if (v2 < v || (v2 == v && p2 < p)) { v = v2; p = p2; }
        }
        if (lane == 0) { topd[r] = v; topi[r] = mi[p]; md[p] = INF; }
        __syncwarp();
    }
    cnt = 0;
    tau = topd[15];
    __syncwarp();
}

__global__ void __launch_bounds__(512) knn_kernel() {
    extern __shared__ char dyn[];
    float4* tile = (float4*)dyn;                           // 2048*16 = 32768
    float*  smd  = (float*)(dyn + 32768);                  // 16*448*4 = 28672
    int*    smi  = (int*)  (dyn + 61440);                  // 28672
    float*  std_ = (float*)(dyn + 90112);                  // 1024
    int*    sti  = (int*)  (dyn + 91136);                  // 1024

    const float INF = __int_as_float(0x7f800000);
    const int tid = threadIdx.x, w = tid >> 5, lane = tid & 31;
    const int b   = blockIdx.x >> 9;
    const int n   = ((blockIdx.x & 511) << 4) | w;         // 16 queries/block

    float* md   = smd  + w*448;  int* mi   = smi + w*448;
    float* topd = std_ + w*16;   int* topi = sti + w*16;

    if (lane < 16) { topd[lane] = INF; topi[lane] = 0; md[432 + lane] = INF; }
    const float4 ci = g_cpack[(b << 13) + n];
    float tau = INF;
    int cnt = 0;
    __syncwarp();

    for (int t = 0; t < 4; t++) {
        __syncthreads();
        for (int q = tid; q < 2048; q += 512)
            tile[q] = g_cneg[(b << 13) + (t << 11) + q];
        __syncthreads();
        #pragma unroll 1
        for (int g = 0; g < 2048; g += 128) {
            const int jb = (t << 11) + g;
            float4 c0 = tile[g + lane];
            float4 c1 = tile[g + lane + 32];
            float4 c2 = tile[g + lane + 64];
            float4 c3 = tile[g + lane + 96];
            float d0 = fmaf(c0.x, ci.x, fmaf(c0.y, ci.y, fmaf(c0.z, ci.z, ci.w + c0.w)));
            float d1 = fmaf(c1.x, ci.x, fmaf(c1.y, ci.y, fmaf(c1.z, ci.z, ci.w + c1.w)));
            float d2 = fmaf(c2.x, ci.x, fmaf(c2.y, ci.y, fmaf(c2.z, ci.z, ci.w + c2.w)));
            float d3 = fmaf(c3.x, ci.x, fmaf(c3.y, ci.y, fmaf(c3.z, ci.z, ci.w + c3.w)));
            if (((n ^ jb) & ~127) == 0) {                  // self is in this group (rare)
                int d = n - jb;                            // 0..127
                if ((d & 31) == lane) {
                    if      (d < 32) d0 = INF;
                    else if (d < 64) d1 = INF;
                    else if (d < 96) d2 = INF;
                    else             d3 = INF;
                }
            }
            if (d0 < tau) { md[lane*13+cnt] = d0; mi[lane*13+cnt] = jb + lane;      cnt++; }
            if (d1 < tau) { md[lane*13+cnt] = d1; mi[lane*13+cnt] = jb + lane + 32; cnt++; }
            if (d2 < tau) { md[lane*13+cnt] = d2; mi[lane*13+cnt] = jb + lane + 64; cnt++; }
            if (d3 < tau) { md[lane*13+cnt] = d3; mi[lane*13+cnt] = jb + lane + 96; cnt++; }
            if (__ballot_sync(0xffffffffu, cnt > 8))
                warp_merge12(md, mi, topd, topi, lane, cnt, tau);
        }
    }
    warp_merge12(md, mi, topd, topi, lane, cnt, tau);
    if (lane < 16) {
        int gofs = ((((b << 13) | n)) << 4) | lane;
        g_idx [gofs] = topi[lane];
        g_dist[gofs] = fmaxf(topd[lane], 0.0f);
    }
}

// ---------------- 1x1 conv (channel GEMM), f32x2 packed, fused BN-stat reduce ----------
template<int CI, int CI0, bool ACT1>
__global__ void __launch_bounds__(256) conv1x1_kernel(
    const float* __restrict__ in0, const float* __restrict__ in1,
    const float* __restrict__ W,   const float* __restrict__ bias,
    const float* __restrict__ sc1, const float* __restrict__ sh1, float slope,
    float* __restrict__ y, int CO, int acc_off) {
    __shared__ __align__(16) float Wsh[CI*32];
    __shared__ float bsh[32];
    __shared__ float scsh[ACT1 ? (CI-CI0) : 1], shsh[ACT1 ? (CI-CI0) : 1];
    __shared__ float red_s[8][32], red_q[8][32];
    const int oc0 = blockIdx.y << 5;
    for (int t = threadIdx.x; t < CI*32; t += 256) {
        int i = t >> 5, ol = t & 31;
        Wsh[t] = W[(oc0 + ol)*CI + i];
    }
    if (threadIdx.x < 32) bsh[threadIdx.x] = bias[oc0 + threadIdx.x];
    if (ACT1 && threadIdx.x < (CI-CI0)) {
        scsh[threadIdx.x] = sc1[threadIdx.x];
        shsh[threadIdx.x] = sh1[threadIdx.x];
    }
    __syncthreads();
    const int p = (blockIdx.x << 8) + threadIdx.x;   // < BB*NN
    const int b = p >> 13, n = p & (NN-1);
    const int w = threadIdx.x >> 5, lane = threadIdx.x & 31;
    unsigned long long acc2[16];
    #pragma unroll
    for (int o2 = 0; o2 < 16; o2++) acc2[o2] = pack2(bsh[2*o2], bsh[2*o2+1]);
    #pragma unroll 2
    for (int i = 0; i < CI0; i++) {
        float x = in0[((b*CI0 + i) << 13) + n];
        unsigned long long x2 = pack2(x, x);
        const unsigned long long* wr = (const unsigned long long*)&Wsh[i << 5];
        #pragma unroll
        for (int o2 = 0; o2 < 16; o2++) acc2[o2] = ffma2(x2, wr[o2], acc2[o2]);
    }
    if (CI > CI0) {
        #pragma unroll 2
        for (int i = 0; i < CI - CI0; i++) {
            float x = in1[((b*(CI-CI0) + i) << 13) + n];
            if (ACT1) {
                x = fmaf(x, scsh[i], shsh[i]);
                x = x > 0.f ? x : slope * x;
            }
            unsigned long long x2 = pack2(x, x);
            const unsigned long long* wr = (const unsigned long long*)&Wsh[(CI0 + i) << 5];
            #pragma unroll
            for (int o2 = 0; o2 < 16; o2++) acc2[o2] = ffma2(x2, wr[o2], acc2[o2]);
        }
    }
    float acc[32];
    #pragma unroll
    for (int o2 = 0; o2 < 16; o2++) {
        float2 u = unpack2(acc2[o2]);
        acc[2*o2] = u.x; acc[2*o2+1] = u.y;
    }
    #pragma unroll
    for (int o = 0; o < 32; o++)
        y[((b*CO + oc0 + o) << 13) + n] = acc[o];

    // fused per-channel sum / sumsq reduction
    #pragma unroll
    for (int o = 0; o < 32; o++) {
        float v = acc[o];
        float q = v * v;
        #pragma unroll
        for (int off = 16; off; off >>= 1) {
            v += __shfl_xor_sync(0xffffffffu, v, off);
            q += __shfl_xor_sync(0xffffffffu, q, off);
        }
        if (lane == 0) { red_s[w][o] = v; red_q[w][o] = q; }
    }
    __syncthreads();
    if (threadIdx.x < 64) {
        int o = threadIdx.x & 31, which = threadIdx.x >> 5;
        float s = 0.f;
        #pragma unroll
        for (int ww = 0; ww < 8; ww++) s += which ? red_q[ww][o] : red_s[ww][o];
        atomicAdd(which ? &g_csum2[acc_off + oc0 + o] : &g_csum[acc_off + oc0 + o], (double)s);
    }
}

// ---------------- finalize BN params from fused sums ----------------
__global__ void bnfin_kernel(int off, int CO,
                             const float* __restrict__ g, const float* __restrict__ bt,
                             float* __restrict__ scale, float* __restrict__ shift) {
    int o = threadIdx.x;
    if (o >= CO) return;
    const double P = (double)(BB*NN);
    double mean = g_csum[off + o] / P;
    double var  = g_csum2[off + o] / P - mean*mean;
    double scl  = (double)g[o] / sqrt(var + 1e-5);
    scale[o] = (float)scl;
    shift[o] = (float)((double)bt[o] - mean*scl);
}

// two sets at once (mlp2 @96, res @224)
__global__ void bnfin2_kernel(const float* __restrict__ g1, const float* __restrict__ bt1,
                              float* __restrict__ sc1, float* __restrict__ sh1,
                              const float* __restrict__ g2, const float* __restrict__ bt2,
                              float* __restrict__ sc2, float* __restrict__ sh2) {
    int t = threadIdx.x;
    const double P = (double)(BB*NN);
    int off = (t < 128) ? 96 : 224;
    int o   = t & 127;
    double mean = g_csum[off + o] / P;
    double var  = g_csum2[off + o] / P - mean*mean;
    const float* gg = (t < 128) ? g1 : g2;
    const float* bb = (t < 128) ? bt1 : bt2;
    double scl = (double)gg[o] / sqrt(var + 1e-5);
    if (t < 128) { sc1[o] = (float)scl; sh1[o] = (float)((double)bb[o] - mean*scl); }
    else         { sc2[o] = (float)scl; sh2[o] = (float)((double)bb[o] - mean*scl); }
}

// ---------------- spatial moments (shared by lse1 & lse2 BN), global accumulate -----------
__global__ void __launch_bounds__(256) moments_kernel() {
    const int tid = threadIdx.x;
    float a[65];
    #pragma unroll
    for (int v = 0; v < 65; v++) a[v] = 0.f;
    const int p0 = (((blockIdx.x << 8) + tid) << 2);
    for (int q = 0; q < 4; q++) {
        int p  = p0 + q;
        int bn = p >> 4;
        int b  = bn >> 13;
        int j  = g_idx[p];
        float d = g_dist[p];
        float4 ct = g_cpack[bn];
        float4 nb = g_cpack[(b << 13) + j];
        float s[10] = { ct.x, ct.y, ct.z, nb.x, nb.y, nb.z,
                        ct.x-nb.x, ct.y-nb.y, ct.z-nb.z, d };
        int c2 = 10;
        #pragma unroll
        for (int i = 0; i < 10; i++) {
            a[i] += s[i];
            #pragma unroll
            for (int j2 = i; j2 < 10; j2++) { a[c2] = fmaf(s[i], s[j2], a[c2]); c2++; }
        }
    }
    __shared__ double sacc[65];
    if (tid < 65) sacc[tid] = 0.0;
    __syncthreads();
    #pragma unroll
    for (int v = 0; v < 65; v++) {
        float x = a[v];
        #pragma unroll
        for (int off = 16; off; off >>= 1) x += __shfl_down_sync(0xffffffffu, x, off);
        if ((tid & 31) == 0) atomicAdd(&sacc[v], (double)x);
    }
    __syncthreads();
    if (tid < 65) atomicAdd(&g_msum[tid], sacc[tid]);
}

// ---------------- finalize lse BN params: mean = w·m + b, var = w^T C w -------------------
// moments/covariance in fp64; per-output matvec in fp32 (error ~1e-7 relative).
__global__ void __launch_bounds__(128) finalize_lse_kernel(
    const float* __restrict__ w1, const float* __restrict__ b1,
    const float* __restrict__ g1, const float* __restrict__ bt1,
    const float* __restrict__ w2, const float* __restrict__ b2,
    const float* __restrict__ g2, const float* __restrict__ bt2) {
    __shared__ double M[65];
    __shared__ float mm[10];
    __shared__ float Cv[10][10];
    const int tid = threadIdx.x;
    if (tid < 65) M[tid] = g_msum[tid];
    __syncthreads();
    const double P = (double)BB * NN * KK;
    __shared__ double mmd[10];
    if (tid < 10) { mmd[tid] = M[tid] / P; }
    __syncthreads();
    if (tid < 10) mm[tid] = (float)mmd[tid];
    if (tid < 100) {
        int i = tid/10, j = tid%10;
        if (j >= i) {
            int off = 10 + i*10 - (i*(i-1))/2 + (j - i);
            float c = (float)(M[off]/P - mmd[i]*mmd[j]);
            Cv[i][j] = c; Cv[j][i] = c;
        }
    }
    __syncthreads();
    if (tid < 64) {
        int o = tid;
        float wv[10];
        #pragma unroll
        for (int i = 0; i < 10; i++) wv[i] = w1[o*10 + i];
        float mean = b1[o];
        #pragma unroll
        for (int i = 0; i < 10; i++) mean = fmaf(wv[i], mm[i], mean);
        float var = 0.f;
        #pragma unroll
        for (int i = 0; i < 10; i++) {
            float t = 0.f;
            #pragma unroll
            for (int j = 0; j < 10; j++) t = fmaf(wv[j], Cv[i][j], t);
            var = fmaf(wv[i], t, var);
        }
        float scl = g1[o] / sqrtf(var + 1e-5f);
        g_l1sc[o] = scl;
        g_l1sh[o] = bt1[o] - mean*scl;
    }
    if (tid >= 64 && tid < 96) {
        int o = tid - 64;
        float wv[10];
        #pragma unroll
        for (int i = 0; i < 10; i++) wv[i] = w2[o*10 + i];
        float mean = b2[o];
        #pragma unroll
        for (int i = 0; i < 10; i++) mean = fmaf(wv[i], mm[i], mean);
        float var = 0.f;
        #pragma unroll
        for (int i = 0; i < 10; i++) {
            float t = 0.f;
            #pragma unroll
            for (int j = 0; j < 10; j++) t = fmaf(wv[j], Cv[i][j], t);
            var = fmaf(wv[i], t, var);
        }
        float scl = g2[o] / sqrtf(var + 1e-5f);
        g_l2sc[o] = scl;
        g_l2sh[o] = bt2[o] - mean*scl;
    }
}

// ---------------- fused LSE (gather + 10->C MLP + BN + ReLU) + attentive pool ----------------
// feat half is constant over K: its score term cancels in softmax, and pooled
// feat channels == feat (handled downstream). Only sf channels computed here.
#define HPAD 20   // padded row length: float4-aligned, bank-conflict degree 4
template<int C>
__global__ void __launch_bounds__(C == 64 ? 128 : 256) lse_pool_kernel(
    const float* __restrict__ Wl,  const float* __restrict__ bl,
    const float* __restrict__ lsc, const float* __restrict__ lsh,
    const float* __restrict__ Wp,  float* __restrict__ pooled) {
    constexpr int WARPS = (C == 64) ? 4 : 8;
    constexpr int CPT   = C / 32;
    constexpr int NT    = WARPS * 32;
    __shared__ float wl_sh[10 * C];
    __shared__ float wp_sh[C * C];        // transposed: [c][o]
    __shared__ float prm_sh[3 * C];
    __shared__ __align__(16) float s_sh[WARPS][16][12];
    __shared__ __align__(16) float h_sh[WARPS][C][HPAD];   // [c][k], padded rows

    const int tid = threadIdx.x;
    for (int t = tid; t < 10*C; t += NT) { int i = t / C, c = t % C; wl_sh[t] = Wl[c*10 + i]; }
    for (int t = tid; t < C*C;  t += NT) { int c = t / C, o = t % C; wp_sh[t] = Wp[o*(2*C) + c]; }
    for (int t = tid; t < C;    t += NT) { prm_sh[t] = bl[t]; prm_sh[C+t] = lsc[t]; prm_sh[2*C+t] = lsh[t]; }
    __syncthreads();

    const int w = tid >> 5, lane = tid & 31;
    const int pt = blockIdx.x * WARPS + w;   // b*NN + n
    const int b  = pt >> 13;
    const int n  = pt & (NN-1);

    // phase 1: gather spatial features (k = lane for lane<16)
    if (lane < 16) {
        int gofs = (pt << 4) | lane;
        int j    = g_idx[gofs];
        float d  = g_dist[gofs];
        float4 ct = g_cpack[pt];
        float4 nb = g_cpack[(b << 13) + j];
        float* sr = s_sh[w][lane];
        sr[0]=ct.x; sr[1]=ct.y; sr[2]=ct.z;
        sr[3]=nb.x; sr[4]=nb.y; sr[5]=nb.z;
        sr[6]=ct.x-nb.x; sr[7]=ct.y-nb.y; sr[8]=ct.z-nb.z;
        sr[9]=d; sr[10]=0.f; sr[11]=0.f;
    }
    __syncwarp();

    // phase 2: 10->C MLP + BN + ReLU -> h_sh[c][k]
    {
        float wlr[CPT][10], br[CPT], scr[CPT], shr[CPT];
        #pragma unroll
        for (int cc = 0; cc < CPT; cc++) {
            int c = lane + 32*cc;
            #pragma unroll
            for (int i = 0; i < 10; i++) wlr[cc][i] = wl_sh[i*C + c];
            br[cc] = prm_sh[c]; scr[cc] = prm_sh[C + c]; shr[cc] = prm_sh[2*C + c];
        }
        #pragma unroll
        for (int k = 0; k < 16; k++) {
            const float4* sp = (const float4*)s_sh[w][k];
            float4 a0 = sp[0], a1 = sp[1], a2 = sp[2];
            float sv[10] = { a0.x,a0.y,a0.z,a0.w, a1.x,a1.y,a1.z,a1.w, a2.x,a2.y };
            #pragma unroll
            for (int cc = 0; cc < CPT; cc++) {
                float yv = br[cc];
                #pragma unroll
                for (int i = 0; i < 10; i++) yv = fmaf(wlr[cc][i], sv[i], yv);
                float v = fmaf(yv, scr[cc], shr[cc]);
                h_sh[w][lane + 32*cc][k] = fmaxf(v, 0.f);
            }
        }
    }
    __syncwarp();

    // phase 3: score GEMM with packed f32x2: scores[o][k] = sum_c Wp[o,c] h[c][k]
    unsigned long long acc2[CPT][8];
    #pragma unroll
    for (int cc = 0; cc < CPT; cc++)
        #pragma unroll
        for (int k2 = 0; k2 < 8; k2++) acc2[cc][k2] = 0ULL;

    #pragma unroll 4
    for (int c = 0; c < C; c++) {
        const unsigned long long* hp = (const unsigned long long*)&h_sh[w][c][0];
        unsigned long long hv2[8];
        #pragma unroll
        for (int k2 = 0; k2 < 8; k2++) hv2[k2] = hp[k2];
        #pragma unroll
        for (int cc = 0; cc < CPT; cc++) {
            float wv = wp_sh[c*C + lane + 32*cc];
            unsigned long long w2 = pack2(wv, wv);
            #pragma unroll
            for (int k2 = 0; k2 < 8; k2++) acc2[cc][k2] = ffma2(w2, hv2[k2], acc2[cc][k2]);
        }
    }

    // phase 4: softmax over K + weighted sum
    #pragma unroll
    for (int cc = 0; cc < CPT; cc++) {
        int o = lane + 32*cc;
        float acc[16];
        #pragma unroll
        for (int k2 = 0; k2 < 8; k2++) {
            float2 u = unpack2(acc2[cc][k2]);
            acc[2*k2] = u.x; acc[2*k2+1] = u.y;
        }
        float m = acc[0];
        #pragma unroll
        for (int k = 1; k < 16; k++) m = fmaxf(m, acc[k]);
        float se = 0.f;
        #pragma unroll
        for (int k = 0; k < 16; k++) { acc[k] = __expf(acc[k] - m); se += acc[k]; }
        const float4* hp = (const float4*)&h_sh[w][o][0];
        float hv[16];
        *(float4*)&hv[0]  = hp[0]; *(float4*)&hv[4]  = hp[1];
        *(float4*)&hv[8]  = hp[2]; *(float4*)&hv[12] = hp[3];
        float sum = 0.f;
        #pragma unroll
        for (int k = 0; k < 16; k++) sum = fmaf(acc[k], hv[k], sum);
        pooled[((b*C + o) << 13) + n] = sum / se;
    }
}

// ---------------- final: BN + ReLU on mlp2 & res, concat write, float4 -------------------
__global__ void __launch_bounds__(256) final_kernel(float4* __restrict__ out) {
    int t = (blockIdx.x << 8) + threadIdx.x;     // < BB*256*NN/4
    int base = t << 2;
    int b  = base >> 21;
    int r  = base & ((1 << 21) - 1);
    int ch = r >> 13;
    int n  = r & (NN-1);
    float4 v;
    float sc, sh;
    if (ch < 128) {
        v = *(const float4*)&g_ymain[((b*128 + ch) << 13) + n];
        sc = g_scm[ch]; sh = g_shm[ch];
    } else {
        int c = ch - 128;
        v = *(const float4*)&g_yres[((b*128 + c) << 13) + n];
        sc = g_scrs[c]; sh = g_shrs[c];
    }
    v.x = fmaxf(fmaf(v.x, sc, sh), 0.f);
    v.y = fmaxf(fmaf(v.y, sc, sh), 0.f);
    v.z = fmaxf(fmaf(v.z, sc, sh), 0.f);
    v.w = fmaxf(fmaf(v.w, sc, sh), 0.f);
    out[t] = v;
}

// ---------------- launch ----------------
extern "C" void kernel_launch(void* const* d_in, const int* in_sizes, int n_in,
                              void* d_out, int out_size) {
    const float* coords   = (const float*)d_in[0];
    const float* features = (const float*)d_in[1];
    const float* mlp1_w  = (const float*)d_in[2];
    const float* mlp1_b  = (const float*)d_in[3];
    const float* mlp1_g  = (const float*)d_in[4];
    const float* mlp1_bt = (const float*)d_in[5];
    const float* lse1_w  = (const float*)d_in[6];
    const float* lse1_b  = (const float*)d_in[7];
    const float* lse1_g  = (const float*)d_in[8];
    const float* lse1_bt = (const float*)d_in[9];
    const float* mlpp1_w  = (const float*)d_in[10];
    const float* mlpp1_b  = (const float*)d_in[11];
    const float* mlpp1_g  = (const float*)d_in[12];
    const float* mlpp1_bt = (const float*)d_in[13];
    const float* lse2_w  = (const float*)d_in[14];
    const float* lse2_b  = (const float*)d_in[15];
    const float* lse2_g  = (const float*)d_in[16];
    const float* lse2_bt = (const float*)d_in[17];
    const float* mlp2_w  = (const float*)d_in[18];
    const float* mlp2_b  = (const float*)d_in[19];
    const float* mlp2_g  = (const float*)d_in[20];
    const float* mlp2_bt = (const float*)d_in[21];
    const float* res_w  = (const float*)d_in[22];
    const float* res_b  = (const float*)d_in[23];
    const float* res_g  = (const float*)d_in[24];
    const float* res_bt = (const float*)d_in[25];
    const float* pool1_w = (const float*)d_in[26];
    // d_in[27] = pool1_b (cancels in softmax; pooled feat half is identity)
    const float* pool2_w = (const float*)d_in[28];
    // d_in[29] = pool2_b
    float* out = (float*)d_out;

    void *p_y1, *p_pool1, *p_y2, *p_pool2, *p_ymain, *p_yres;
    void *p_sc1, *p_sh1, *p_sc2, *p_sh2, *p_scm, *p_shm, *p_scrs, *p_shrs;
    void *p_l1sc, *p_l1sh, *p_l2sc, *p_l2sh;
    cudaGetSymbolAddress(&p_y1, g_y1);       cudaGetSymbolAddress(&p_pool1, g_pool1);
    cudaGetSymbolAddress(&p_y2, g_y2);       cudaGetSymbolAddress(&p_pool2, g_pool2);
    cudaGetSymbolAddress(&p_ymain, g_ymain); cudaGetSymbolAddress(&p_yres, g_yres);
    cudaGetSymbolAddress(&p_sc1, g_sc1);     cudaGetSymbolAddress(&p_sh1, g_sh1);
    cudaGetSymbolAddress(&p_sc2, g_sc2);     cudaGetSymbolAddress(&p_sh2, g_sh2);
    cudaGetSymbolAddress(&p_scm, g_scm);     cudaGetSymbolAddress(&p_shm, g_shm);
    cudaGetSymbolAddress(&p_scrs, g_scrs);   cudaGetSymbolAddress(&p_shrs, g_shrs);
    cudaGetSymbolAddress(&p_l1sc, g_l1sc);   cudaGetSymbolAddress(&p_l1sh, g_l1sh);
    cudaGetSymbolAddress(&p_l2sc, g_l2sc);   cudaGetSymbolAddress(&p_l2sh, g_l2sh);

    static bool attr_done = false;
    if (!attr_done) {
        cudaFuncSetAttribute(knn_kernel, cudaFuncAttributeMaxDynamicSharedMemorySize, 92160);
        attr_done = true;
    }

    // geometry (also zeros accumulators)
    pack_kernel<<<64, 256>>>(coords);
    knn_kernel<<<1024, 512, 92160>>>();
    moments_kernel<<<256, 256>>>();
    finalize_lse_kernel<<<1, 128>>>(lse1_w, lse1_b, lse1_g, lse1_bt,
                                    lse2_w, lse2_b, lse2_g, lse2_bt);

    // mlp1: features(32) -> 64, stats fused
    conv1x1_kernel<32,32,false><<<dim3(64,2), 256>>>(features, nullptr, mlp1_w, mlp1_b,
                                                     nullptr, nullptr, 0.f, (float*)p_y1, 64, 0);
    bnfin_kernel<<<1, 64>>>(0, 64, mlp1_g, mlp1_bt, (float*)p_sc1, (float*)p_sh1);

    // lse1 + pool1 (sf half only)
    lse_pool_kernel<64><<<4096, 128>>>(lse1_w, lse1_b, (float*)p_l1sc, (float*)p_l1sh,
                                       pool1_w, (float*)p_pool1);

    // mlpp1: [pool1_sf(64); bn+leaky0.2(y1)(64)] -> 32, stats fused
    conv1x1_kernel<128,64,true><<<dim3(64,1), 256>>>((float*)p_pool1, (float*)p_y1, mlpp1_w, mlpp1_b,
                                                     (float*)p_sc1, (float*)p_sh1, 0.2f, (float*)p_y2, 32, 64);
    bnfin_kernel<<<1, 32>>>(64, 32, mlpp1_g, mlpp1_bt, (float*)p_sc2, (float*)p_sh2);

    // lse2 + pool2
    lse_pool_kernel<32><<<2048, 256>>>(lse2_w, lse2_b, (float*)p_l2sc, (float*)p_l2sh,
                                       pool2_w, (float*)p_pool2);

    // mlp2: [pool2_sf(32); bn+relu(y2)(32)] -> 128, stats fused
    conv1x1_kernel<64,32,true><<<dim3(64,4), 256>>>((float*)p_pool2, (float*)p_y2, mlp2_w, mlp2_b,
                                                    (float*)p_sc2, (float*)p_sh2, 0.0f, (float*)p_ymain, 128, 96);
    // residual: features(32) -> 128, stats fused
    conv1x1_kernel<32,32,false><<<dim3(64,4), 256>>>(features, nullptr, res_w, res_b,
                                                     nullptr, nullptr, 0.f, (float*)p_yres, 128, 224);
    bnfin2_kernel<<<1, 256>>>(mlp2_g, mlp2_bt, (float*)p_scm, (float*)p_shm,
                              res_g, res_bt, (float*)p_scrs, (float*)p_shrs);

    // fused BN + ReLU + concat (+ identity leaky 0.01), float4
    final_kernel<<<4096, 256>>>((float4*)out);
}